// round 4
// baseline (speedup 1.0000x reference)
#include <cuda_runtime.h>
#include <cuda_bf16.h>
#include <math.h>

// Problem constants (fixed by the benchmark's setup_inputs)
#define C_CLASSES 16
#define D_DIM     256
#define N_MAX     32768
#define N_TILES   10          // upper-triangle 64x64 tiles of a 256x256 gram
#define LAM   25.0f
#define MU    25.0f
#define NU     1.0f
#define ALPHA 50.0f
#define EPS_V  1e-4f

// ---------------- scratch (device globals; no allocation allowed) ----------
__device__ int   g_counts[C_CLASSES];
__device__ int   g_offsets[C_CLASSES];
__device__ int   g_cursor[C_CLASSES];
__device__ int   g_idx[N_MAX];
__device__ float g_sp[4][2][C_CLASSES][D_DIM];   // chunked partial sums
__device__ float g_qp[4][2][C_CLASSES][D_DIM];   // chunked partial sumsq
__device__ float g_mean[2 * C_CLASSES * D_DIM];  // [view][class][d]
__device__ float g_var [2 * C_CLASSES * D_DIM];
__device__ float g_inv_partial[128];
__device__ float g_cov_partial[2 * C_CLASSES * N_TILES];
__device__ __nv_bfloat16 g_a16[N_MAX * D_DIM];
__device__ __nv_bfloat16 g_b16[N_MAX * D_DIM];

// ---------------- helpers ---------------------------------------------------
__device__ __forceinline__ float block_reduce_256(float v, float* red) {
    int tid = threadIdx.x;
    red[tid] = v;
    __syncthreads();
    #pragma unroll
    for (int s = 128; s > 0; s >>= 1) {
        if (tid < s) red[tid] += red[tid + s];
        __syncthreads();
    }
    float r = red[0];
    __syncthreads();
    return r;
}

__device__ __forceinline__ void ldsm4t(unsigned& r0, unsigned& r1,
                                       unsigned& r2, unsigned& r3,
                                       unsigned addr) {
    asm volatile("ldmatrix.sync.aligned.m8n8.x4.trans.shared.b16 {%0,%1,%2,%3}, [%4];\n"
                 : "=r"(r0), "=r"(r1), "=r"(r2), "=r"(r3) : "r"(addr));
}

__device__ __forceinline__ void mma16816(float* c, unsigned a0, unsigned a1,
                                         unsigned a2, unsigned a3,
                                         unsigned b0, unsigned b1) {
    asm volatile("mma.sync.aligned.m16n8k16.row.col.f32.bf16.bf16.f32 "
                 "{%0,%1,%2,%3}, {%4,%5,%6,%7}, {%8,%9}, {%0,%1,%2,%3};\n"
                 : "+f"(c[0]), "+f"(c[1]), "+f"(c[2]), "+f"(c[3])
                 : "r"(a0), "r"(a1), "r"(a2), "r"(a3), "r"(b0), "r"(b1));
}

__device__ __forceinline__ void cpa16(void* dst, const void* src, bool pred) {
    unsigned d = (unsigned)__cvta_generic_to_shared(dst);
    int sz = pred ? 16 : 0;
    asm volatile("cp.async.cg.shared.global [%0], [%1], 16, %2;\n"
                 :: "r"(d), "l"(src), "r"(sz));
}
__device__ __forceinline__ void cpa_commit() {
    asm volatile("cp.async.commit_group;\n");
}
__device__ __forceinline__ void cpa_wait1() {
    asm volatile("cp.async.wait_group 1;\n");
}

// ---------------- K0: zero class counters -----------------------------------
__global__ void k0_zero() {
    int t = threadIdx.x;
    if (t < C_CLASSES) g_counts[t] = 0;
}

// ---------------- K1: histogram + invariance + bf16 conversion --------------
__global__ void k1_inv_hist_cvt(const float* __restrict__ za,
                                const float* __restrict__ zb,
                                const int* __restrict__ labels, int N) {
    __shared__ int h[C_CLASSES];
    __shared__ float red[256];
    int tid = threadIdx.x;
    int gid = blockIdx.x * 256 + tid;
    if (tid < C_CLASSES) h[tid] = 0;
    __syncthreads();

    if (gid < N) atomicAdd(&h[labels[gid]], 1);

    const float4* a4 = (const float4*)za;
    const float4* b4 = (const float4*)zb;
    __nv_bfloat162* a16 = (__nv_bfloat162*)g_a16;
    __nv_bfloat162* b16 = (__nv_bfloat162*)g_b16;
    long total4 = (long)N * (D_DIM / 4);
    long stride = (long)gridDim.x * 256;
    float s = 0.f;
    for (long e = gid; e < total4; e += stride) {
        float4 a = a4[e], b = b4[e];
        float dx = a.x - b.x, dy = a.y - b.y, dz = a.z - b.z, dw = a.w - b.w;
        s += dx * dx + dy * dy + dz * dz + dw * dw;
        a16[2 * e]     = __floats2bfloat162_rn(a.x, a.y);
        a16[2 * e + 1] = __floats2bfloat162_rn(a.z, a.w);
        b16[2 * e]     = __floats2bfloat162_rn(b.x, b.y);
        b16[2 * e + 1] = __floats2bfloat162_rn(b.z, b.w);
    }
    __syncthreads();
    if (tid < C_CLASSES && h[tid] > 0) atomicAdd(&g_counts[tid], h[tid]);
    s = block_reduce_256(s, red);
    if (tid == 0) g_inv_partial[blockIdx.x] = s;
}

// ---------------- K2: prefix over 16 class counts ---------------------------
__global__ void k2_prefix() {
    if (threadIdx.x == 0) {
        int o = 0;
        for (int c = 0; c < C_CLASSES; c++) {
            g_offsets[c] = o;
            g_cursor[c]  = o;
            o += g_counts[c];
        }
    }
}

// ---------------- K3: scatter with smem-aggregated cursors ------------------
__global__ void k3_scatter(const int* __restrict__ labels, int N) {
    __shared__ int cnt[C_CLASSES];
    __shared__ int basev[C_CLASSES];
    int tid = threadIdx.x;
    int gid = blockIdx.x * 256 + tid;
    if (tid < C_CLASSES) cnt[tid] = 0;
    __syncthreads();
    int lab = -1, my = 0;
    if (gid < N) {
        lab = labels[gid];
        my = atomicAdd(&cnt[lab], 1);
    }
    __syncthreads();
    if (tid < C_CLASSES && cnt[tid] > 0)
        basev[tid] = atomicAdd(&g_cursor[tid], cnt[tid]);
    __syncthreads();
    if (gid < N)
        g_idx[basev[lab] + my] = gid;
}

// ---------------- K4: per-class partial sums from bf16 (L2-resident) --------
__global__ void __launch_bounds__(256) k4_stats() {
    int c = blockIdx.x, v = blockIdx.y, ch = blockIdx.z;
    const __nv_bfloat16* __restrict__ x = v ? g_b16 : g_a16;
    int n    = g_counts[c];
    int base = g_offsets[c];
    int per  = (n + 3) >> 2;
    int lo = ch * per;
    int hi = min(n, lo + per);
    int d = threadIdx.x;
    float s = 0.f, q = 0.f;
    int i = lo;
    for (; i + 4 <= hi; i += 4) {
        int r0 = g_idx[base + i + 0];
        int r1 = g_idx[base + i + 1];
        int r2 = g_idx[base + i + 2];
        int r3 = g_idx[base + i + 3];
        float v0 = __bfloat162float(x[(long)r0 * D_DIM + d]);
        float v1 = __bfloat162float(x[(long)r1 * D_DIM + d]);
        float v2 = __bfloat162float(x[(long)r2 * D_DIM + d]);
        float v3 = __bfloat162float(x[(long)r3 * D_DIM + d]);
        s += v0 + v1 + v2 + v3;
        q += v0 * v0 + v1 * v1 + v2 * v2 + v3 * v3;
    }
    for (; i < hi; i++) {
        float vv = __bfloat162float(x[(long)g_idx[base + i] * D_DIM + d]);
        s += vv;
        q += vv * vv;
    }
    g_sp[ch][v][c][d] = s;
    g_qp[ch][v][c][d] = q;
}

// ---------------- K4b: reduce partials -> mean/var --------------------------
__global__ void k4b_meanvar() {
    int o = blockIdx.x * 256 + threadIdx.x;   // grid 32 -> 8192 entries
    int d = o & (D_DIM - 1);
    int c = (o >> 8) & (C_CLASSES - 1);
    int v = o >> 12;
    float s = g_sp[0][v][c][d] + g_sp[1][v][c][d] + g_sp[2][v][c][d] + g_sp[3][v][c][d];
    float q = g_qp[0][v][c][d] + g_qp[1][v][c][d] + g_qp[2][v][c][d] + g_qp[3][v][c][d];
    float fn = (float)g_counts[c];
    float m = s / fn;
    g_mean[o] = m;
    g_var[o]  = (q - fn * m * m) / (fn - 1.f);
}

// ---------------- K5: bf16 tensor-core gram, cp.async double-buffered -------
// Block = (tile 0..9, class, view). 64x64 tile, 8 warps, mma.m16n8k16 bf16.
// K-chunk 64, 2 smem stages, cp.async overlaps gather with MMA.
__constant__ int c_ti[N_TILES] = {0,0,0,0,1,1,1,2,2,3};
__constant__ int c_tj[N_TILES] = {0,1,2,3,1,2,3,2,3,3};

#define KCHUNK 64

__global__ void __launch_bounds__(256) k5_gram() {
    int t = blockIdx.x;
    int c = blockIdx.y;
    int v = blockIdx.z;
    const __nv_bfloat16* __restrict__ x = v ? g_b16 : g_a16;
    int ti = c_ti[t], tj = c_tj[t];

    __shared__ __nv_bfloat16 As[2][KCHUNK][72];
    __shared__ __nv_bfloat16 Bs[2][KCHUNK][72];
    __shared__ float red[256];

    int n    = g_counts[c];
    int base = g_offsets[c];
    int tid  = threadIdx.x;
    int lane = tid & 31;
    int warp = tid >> 5;

    int m0 = (warp >> 1) * 16;     // warp's m-block within 64
    int nh = (warp & 1) * 32;      // warp's n-half within 64

    unsigned aBase = (unsigned)__cvta_generic_to_shared(&As[0][0][0]);
    unsigned bBase = (unsigned)__cvta_generic_to_shared(&Bs[0][0][0]);
    const unsigned STAGE = KCHUNK * 72 * 2;   // bytes per stage
    int a_row = (lane & 7) + ((lane >> 4) & 1) * 8;          // k within 16
    int a_col = m0 + ((lane >> 3) & 1) * 8;                  // m
    unsigned aAddr = aBase + (unsigned)(a_row * 72 + a_col) * 2u;
    int b_row = (lane & 7) + ((lane >> 3) & 1) * 8;          // k within 16
    int b_col = nh + ((lane >> 4) & 1) * 8;                  // n
    unsigned bAddr0 = bBase + (unsigned)(b_row * 72 + b_col) * 2u;
    unsigned bAddr1 = bAddr0 + 16u * 2u;                     // n-tiles +16

    // staging: thread covers rows kr0 and kr0+32, one 16B segment each (A+B)
    int kr0 = tid >> 3;    // 0..31
    int seg = tid & 7;     // 0..7

    int nchunks = (n + KCHUNK - 1) / KCHUNK;

    // ---- issue chunk ci into stage s ----
    #define ISSUE(ci, s) do {                                              \
        int _c0 = (ci) * KCHUNK;                                           \
        _Pragma("unroll")                                                  \
        for (int u = 0; u < 2; u++) {                                      \
            int kr = kr0 + u * 32;                                         \
            int kk = _c0 + kr;                                             \
            bool pv = kk < n;                                              \
            int r = pv ? g_idx[base + kk] : 0;                             \
            const __nv_bfloat16* rp = x + (long)r * D_DIM;                 \
            cpa16(&As[s][kr][seg * 8], rp + ti * 64 + seg * 8, pv);        \
            cpa16(&Bs[s][kr][seg * 8], rp + tj * 64 + seg * 8, pv);        \
        }                                                                  \
    } while (0)

    float acc[4][4] = {};  // [n-tile 0..3][c0..c3]

    ISSUE(0, 0);
    cpa_commit();
    for (int ci = 0; ci < nchunks; ci++) {
        if (ci + 1 < nchunks) ISSUE(ci + 1, (ci + 1) & 1);
        cpa_commit();
        cpa_wait1();
        __syncthreads();
        unsigned sOff = (unsigned)(ci & 1) * STAGE;
        #pragma unroll
        for (int ks = 0; ks < KCHUNK; ks += 16) {
            unsigned off = sOff + (unsigned)(ks * 72) * 2u;
            unsigned a0, a1, a2, a3;
            unsigned p0, p1, p2, p3;
            unsigned q0, q1, q2, q3;
            ldsm4t(a0, a1, a2, a3, aAddr + off);
            ldsm4t(p0, p1, p2, p3, bAddr0 + off);
            ldsm4t(q0, q1, q2, q3, bAddr1 + off);
            mma16816(acc[0], a0, a1, a2, a3, p0, p1);
            mma16816(acc[1], a0, a1, a2, a3, p2, p3);
            mma16816(acc[2], a0, a1, a2, a3, q0, q1);
            mma16816(acc[3], a0, a1, a2, a3, q2, q3);
        }
        __syncthreads();
    }

    // cov correction + squared off-diagonal contribution
    int vc = v * C_CLASSES + c;
    const float* mrow = &g_mean[vc * D_DIM];
    int g  = lane >> 2;       // 0..7
    int tg = lane & 3;        // 0..3
    float fn = (float)n;
    float inv_nm1 = 1.f / (fn - 1.f);
    float wgt_tile = (ti == tj) ? 1.f : 2.f;
    float mi0 = mrow[ti * 64 + m0 + g];
    float mi1 = mrow[ti * 64 + m0 + g + 8];
    int gi0 = ti * 64 + m0 + g;
    int gi1 = gi0 + 8;
    float contrib = 0.f;
    #pragma unroll
    for (int nt = 0; nt < 4; nt++) {
        int n0 = nh + nt * 8;
        int gj0 = tj * 64 + n0 + 2 * tg;
        float mj0 = mrow[tj * 64 + n0 + 2 * tg];
        float mj1 = mrow[tj * 64 + n0 + 2 * tg + 1];
        float cv;
        cv = (acc[nt][0] - fn * mi0 * mj0) * inv_nm1;
        contrib += ((gi0 == gj0)     ? 0.f : wgt_tile) * cv * cv;
        cv = (acc[nt][1] - fn * mi0 * mj1) * inv_nm1;
        contrib += ((gi0 == gj0 + 1) ? 0.f : wgt_tile) * cv * cv;
        cv = (acc[nt][2] - fn * mi1 * mj0) * inv_nm1;
        contrib += ((gi1 == gj0)     ? 0.f : wgt_tile) * cv * cv;
        cv = (acc[nt][3] - fn * mi1 * mj1) * inv_nm1;
        contrib += ((gi1 == gj0 + 1) ? 0.f : wgt_tile) * cv * cv;
    }
    contrib = block_reduce_256(contrib, red);
    if (tid == 0)
        g_cov_partial[vc * N_TILES + t] = contrib;
}

// ---------------- K6: finalize all terms ------------------------------------
__global__ void k6_final(float* __restrict__ out, int N) {
    __shared__ float m[C_CLASSES * D_DIM];
    __shared__ float red[256];
    int tid = threadIdx.x;

    for (int e = tid; e < C_CLASSES * D_DIM; e += 256)
        m[e] = 0.5f * (g_mean[e] + g_mean[C_CLASSES * D_DIM + e]);

    // invariance (128 partials)
    float inv_sum = block_reduce_256(tid < 128 ? g_inv_partial[tid] : 0.f, red);

    // variance
    float vsum = 0.f;
    for (int e = tid; e < 2 * C_CLASSES * D_DIM; e += 256) {
        float vv = g_var[e];
        vsum += fmaxf(0.f, 1.f - sqrtf(vv + EPS_V));
    }
    vsum = block_reduce_256(vsum, red);

    // covariance
    float csum = 0.f;
    for (int e = tid; e < 2 * C_CLASSES * N_TILES; e += 256)
        csum += g_cov_partial[e];
    csum = block_reduce_256(csum, red);

    // class-discriminative margin (120 pairs)
    float psum = 0.f;
    const int npairs = C_CLASSES * (C_CLASSES - 1) / 2;
    if (tid < npairs) {
        int i = 0, rem = tid;
        while (rem >= C_CLASSES - 1 - i) { rem -= C_CLASSES - 1 - i; i++; }
        int j = i + 1 + rem;
        float d2 = 0.f;
        for (int d = 0; d < D_DIM; d++) {
            float df = m[i * D_DIM + d] - m[j * D_DIM + d];
            d2 += df * df;
        }
        float dist = sqrtf(d2);
        float rr = fmaxf(0.f, ALPHA - dist);
        psum = rr * rr;
    }
    psum = block_reduce_256(psum, red);

    if (tid == 0) {
        float inv_loss   = inv_sum / ((float)N * (float)D_DIM);
        float var_loss   = vsum * 0.5f / ((float)C_CLASSES * (float)D_DIM);
        float cov_loss   = csum * 0.5f / ((float)C_CLASSES * (float)D_DIM);
        float class_loss = psum / (float)npairs;
        out[0] = LAM * inv_loss + MU * var_loss + NU * cov_loss + ALPHA * class_loss;
    }
}

// ---------------- launch -----------------------------------------------------
extern "C" void kernel_launch(void* const* d_in, const int* in_sizes, int n_in,
                              void* d_out, int out_size) {
    const float* za     = (const float*)d_in[0];
    const float* zb     = (const float*)d_in[1];
    const int*   labels = (const int*)d_in[2];
    int N = in_sizes[2];   // labels element count

    k0_zero<<<1, 32>>>();
    k1_inv_hist_cvt<<<128, 256>>>(za, zb, labels, N);
    k2_prefix<<<1, 32>>>();
    k3_scatter<<<(N + 255) / 256, 256>>>(labels, N);
    k4_stats<<<dim3(C_CLASSES, 2, 4), 256>>>();
    k4b_meanvar<<<32, 256>>>();
    k5_gram<<<dim3(N_TILES, C_CLASSES, 2), 256>>>();
    k6_final<<<1, 256>>>((float*)d_out, N);
}

// round 5
// speedup vs baseline: 1.3877x; 1.3877x over previous
#include <cuda_runtime.h>
#include <cuda_bf16.h>
#include <math.h>

// Problem constants (fixed by the benchmark's setup_inputs)
#define C_CLASSES 16
#define D_DIM     256
#define N_MAX     32768
#define N_TILES   10          // upper-triangle 64x64 tiles of a 256x256 gram
#define LAM   25.0f
#define MU    25.0f
#define NU     1.0f
#define ALPHA 50.0f
#define EPS_V  1e-4f

#define K4_CH 16              // k4 row-chunk splits per (class,view)

// ---------------- scratch (device globals; no allocation allowed) ----------
__device__ int   g_counts[C_CLASSES];
__device__ int   g_offsets[C_CLASSES];
__device__ int   g_cursor[C_CLASSES];
__device__ float g_sp[K4_CH][2][C_CLASSES][D_DIM];  // chunked partial sums
__device__ float g_qp[K4_CH][2][C_CLASSES][D_DIM];  // chunked partial sumsq
__device__ float g_mean[2 * C_CLASSES * D_DIM];     // [view][class][d]
__device__ float g_var [2 * C_CLASSES * D_DIM];
__device__ float g_inv_partial[256];
__device__ float g_cov_partial[2 * C_CLASSES * N_TILES];
__device__ __nv_bfloat16 g_xa[N_MAX * D_DIM];       // class-sorted bf16 rows
__device__ __nv_bfloat16 g_xb[N_MAX * D_DIM];

// ---------------- helpers ---------------------------------------------------
__device__ __forceinline__ float block_reduce_256(float v, float* red) {
    int tid = threadIdx.x;
    red[tid] = v;
    __syncthreads();
    #pragma unroll
    for (int s = 128; s > 0; s >>= 1) {
        if (tid < s) red[tid] += red[tid + s];
        __syncthreads();
    }
    float r = red[0];
    __syncthreads();
    return r;
}

__device__ __forceinline__ void ldsm4t(unsigned& r0, unsigned& r1,
                                       unsigned& r2, unsigned& r3,
                                       unsigned addr) {
    asm volatile("ldmatrix.sync.aligned.m8n8.x4.trans.shared.b16 {%0,%1,%2,%3}, [%4];\n"
                 : "=r"(r0), "=r"(r1), "=r"(r2), "=r"(r3) : "r"(addr));
}

__device__ __forceinline__ void mma16816(float* c, unsigned a0, unsigned a1,
                                         unsigned a2, unsigned a3,
                                         unsigned b0, unsigned b1) {
    asm volatile("mma.sync.aligned.m16n8k16.row.col.f32.bf16.bf16.f32 "
                 "{%0,%1,%2,%3}, {%4,%5,%6,%7}, {%8,%9}, {%0,%1,%2,%3};\n"
                 : "+f"(c[0]), "+f"(c[1]), "+f"(c[2]), "+f"(c[3])
                 : "r"(a0), "r"(a1), "r"(a2), "r"(a3), "r"(b0), "r"(b1));
}

__device__ __forceinline__ void cpa16(void* dst, const void* src, bool pred) {
    unsigned d = (unsigned)__cvta_generic_to_shared(dst);
    int sz = pred ? 16 : 0;
    asm volatile("cp.async.cg.shared.global [%0], [%1], 16, %2;\n"
                 :: "r"(d), "l"(src), "r"(sz));
}
__device__ __forceinline__ void cpa_commit() {
    asm volatile("cp.async.commit_group;\n");
}
__device__ __forceinline__ void cpa_wait1() {
    asm volatile("cp.async.wait_group 1;\n");
}

__device__ __forceinline__ unsigned pack_bf162(float x, float y) {
    __nv_bfloat162 h = __floats2bfloat162_rn(x, y);
    return *reinterpret_cast<unsigned*>(&h);
}

// ---------------- K0: zero class counters -----------------------------------
__global__ void k0_zero() {
    int t = threadIdx.x;
    if (t < C_CLASSES) g_counts[t] = 0;
}

// ---------------- K1: labels histogram (128 KB read) ------------------------
__global__ void k1_hist(const int* __restrict__ labels, int N) {
    __shared__ int h[C_CLASSES];
    int tid = threadIdx.x;
    if (tid < C_CLASSES) h[tid] = 0;
    __syncthreads();
    for (int r = blockIdx.x * 256 + tid; r < N; r += gridDim.x * 256)
        atomicAdd(&h[labels[r]], 1);
    __syncthreads();
    if (tid < C_CLASSES && h[tid] > 0) atomicAdd(&g_counts[tid], h[tid]);
}

// ---------------- K2: prefix over 16 class counts ---------------------------
__global__ void k2_prefix() {
    if (threadIdx.x == 0) {
        int o = 0;
        for (int c = 0; c < C_CLASSES; c++) {
            g_offsets[c] = o;
            g_cursor[c]  = o;
            o += g_counts[c];
        }
    }
}

// ---------------- K1b: convert + class-sorted scatter + invariance ----------
// One warp per row: 32 lanes x 2 float4 per view; bf16 row written contiguously
// to its class-sorted position (rank from atomic cursor).
__global__ void __launch_bounds__(256) k1b_cvt(const float* __restrict__ za,
                                               const float* __restrict__ zb,
                                               const int* __restrict__ labels,
                                               int N) {
    __shared__ float red[256];
    int tid  = threadIdx.x;
    int lane = tid & 31;
    int warp = tid >> 5;
    int gw = blockIdx.x * 8 + warp;
    int nw = gridDim.x * 8;

    float s = 0.f;
    for (int r = gw; r < N; r += nw) {
        int pos = 0;
        if (lane == 0) pos = atomicAdd(&g_cursor[labels[r]], 1);
        pos = __shfl_sync(0xffffffffu, pos, 0);

        const float4* pa = (const float4*)(za + (long)r * D_DIM);
        const float4* pb = (const float4*)(zb + (long)r * D_DIM);
        float4 a0 = pa[lane * 2], a1 = pa[lane * 2 + 1];
        float4 b0 = pb[lane * 2], b1 = pb[lane * 2 + 1];

        float dx = a0.x - b0.x, dy = a0.y - b0.y, dz = a0.z - b0.z, dw = a0.w - b0.w;
        s += dx * dx + dy * dy + dz * dz + dw * dw;
        dx = a1.x - b1.x; dy = a1.y - b1.y; dz = a1.z - b1.z; dw = a1.w - b1.w;
        s += dx * dx + dy * dy + dz * dz + dw * dw;

        uint4 wa, wb;
        wa.x = pack_bf162(a0.x, a0.y); wa.y = pack_bf162(a0.z, a0.w);
        wa.z = pack_bf162(a1.x, a1.y); wa.w = pack_bf162(a1.z, a1.w);
        wb.x = pack_bf162(b0.x, b0.y); wb.y = pack_bf162(b0.z, b0.w);
        wb.z = pack_bf162(b1.x, b1.y); wb.w = pack_bf162(b1.z, b1.w);
        ((uint4*)(g_xa + (long)pos * D_DIM))[lane] = wa;
        ((uint4*)(g_xb + (long)pos * D_DIM))[lane] = wb;
    }
    s = block_reduce_256(s, red);
    if (tid == 0) g_inv_partial[blockIdx.x] = s;
}

// ---------------- K4: streaming per-class partial sums (bf16, L2) -----------
__global__ void __launch_bounds__(128) k4_stats() {
    int c = blockIdx.x, v = blockIdx.y, ch = blockIdx.z;
    const __nv_bfloat16* __restrict__ x = v ? g_xb : g_xa;
    int n    = g_counts[c];
    int base = g_offsets[c];
    int per  = (n + K4_CH - 1) / K4_CH;
    int lo = ch * per;
    int hi = min(n, lo + per);
    int t = threadIdx.x;                 // 0..127 -> dims 2t, 2t+1
    float s0 = 0.f, s1 = 0.f, q0 = 0.f, q1 = 0.f;
    const __nv_bfloat162* __restrict__ xp =
        (const __nv_bfloat162*)(x + (long)base * D_DIM) + t;
    int i = lo;
    #pragma unroll 8
    for (; i < hi; i++) {
        __nv_bfloat162 h = xp[(long)i * (D_DIM / 2)];
        float v0 = __bfloat162float(h.x);
        float v1 = __bfloat162float(h.y);
        s0 += v0; q0 += v0 * v0;
        s1 += v1; q1 += v1 * v1;
    }
    g_sp[ch][v][c][2 * t]     = s0;
    g_sp[ch][v][c][2 * t + 1] = s1;
    g_qp[ch][v][c][2 * t]     = q0;
    g_qp[ch][v][c][2 * t + 1] = q1;
}

// ---------------- K4b: reduce partials -> mean/var --------------------------
__global__ void k4b_meanvar() {
    int o = blockIdx.x * 256 + threadIdx.x;   // grid 32 -> 8192 entries
    int d = o & (D_DIM - 1);
    int c = (o >> 8) & (C_CLASSES - 1);
    int v = o >> 12;
    float s = 0.f, q = 0.f;
    #pragma unroll
    for (int ch = 0; ch < K4_CH; ch++) {
        s += g_sp[ch][v][c][d];
        q += g_qp[ch][v][c][d];
    }
    float fn = (float)g_counts[c];
    float m = s / fn;
    g_mean[o] = m;
    g_var[o]  = (q - fn * m * m) / (fn - 1.f);
}

// ---------------- K5: bf16 tensor-core gram, contiguous rows, cp.async ------
// Block = (tile 0..9, class, view). 64x64 tile, 8 warps, mma.m16n8k16 bf16.
// Rows are class-sorted -> loads are pure arithmetic (no index indirection).
__constant__ int c_ti[N_TILES] = {0,0,0,0,1,1,1,2,2,3};
__constant__ int c_tj[N_TILES] = {0,1,2,3,1,2,3,2,3,3};

#define KCHUNK 64

__global__ void __launch_bounds__(256) k5_gram() {
    int t = blockIdx.x;
    int c = blockIdx.y;
    int v = blockIdx.z;
    const __nv_bfloat16* __restrict__ x = v ? g_xb : g_xa;
    int ti = c_ti[t], tj = c_tj[t];

    __shared__ __nv_bfloat16 As[2][KCHUNK][72];
    __shared__ __nv_bfloat16 Bs[2][KCHUNK][72];
    __shared__ float red[256];

    int n    = g_counts[c];
    int base = g_offsets[c];
    int tid  = threadIdx.x;
    int lane = tid & 31;
    int warp = tid >> 5;

    int m0 = (warp >> 1) * 16;     // warp's m-block within 64
    int nh = (warp & 1) * 32;      // warp's n-half within 64

    unsigned aBase = (unsigned)__cvta_generic_to_shared(&As[0][0][0]);
    unsigned bBase = (unsigned)__cvta_generic_to_shared(&Bs[0][0][0]);
    const unsigned STAGE = KCHUNK * 72 * 2;   // bytes per stage
    int a_row = (lane & 7) + ((lane >> 4) & 1) * 8;          // k within 16
    int a_col = m0 + ((lane >> 3) & 1) * 8;                  // m
    unsigned aAddr = aBase + (unsigned)(a_row * 72 + a_col) * 2u;
    int b_row = (lane & 7) + ((lane >> 3) & 1) * 8;          // k within 16
    int b_col = nh + ((lane >> 4) & 1) * 8;                  // n
    unsigned bAddr0 = bBase + (unsigned)(b_row * 72 + b_col) * 2u;
    unsigned bAddr1 = bAddr0 + 16u * 2u;                     // n-tiles +16

    // staging: thread covers rows kr0 and kr0+32, one 16B segment each (A+B)
    int kr0 = tid >> 3;    // 0..31
    int seg = tid & 7;     // 0..7

    int nchunks = (n + KCHUNK - 1) / KCHUNK;

    #define ISSUE(ci, s) do {                                              \
        int _c0 = (ci) * KCHUNK;                                           \
        _Pragma("unroll")                                                  \
        for (int u = 0; u < 2; u++) {                                      \
            int kr = kr0 + u * 32;                                         \
            int kk = _c0 + kr;                                             \
            bool pv = kk < n;                                              \
            const __nv_bfloat16* rp = x + (long)(base + kk) * D_DIM;       \
            cpa16(&As[s][kr][seg * 8], rp + ti * 64 + seg * 8, pv);        \
            cpa16(&Bs[s][kr][seg * 8], rp + tj * 64 + seg * 8, pv);        \
        }                                                                  \
    } while (0)

    float acc[4][4] = {};  // [n-tile 0..3][c0..c3]

    ISSUE(0, 0);
    cpa_commit();
    for (int ci = 0; ci < nchunks; ci++) {
        if (ci + 1 < nchunks) ISSUE(ci + 1, (ci + 1) & 1);
        cpa_commit();
        cpa_wait1();
        __syncthreads();
        unsigned sOff = (unsigned)(ci & 1) * STAGE;
        #pragma unroll
        for (int ks = 0; ks < KCHUNK; ks += 16) {
            unsigned off = sOff + (unsigned)(ks * 72) * 2u;
            unsigned a0, a1, a2, a3;
            unsigned p0, p1, p2, p3;
            unsigned q0, q1, q2, q3;
            ldsm4t(a0, a1, a2, a3, aAddr + off);
            ldsm4t(p0, p1, p2, p3, bAddr0 + off);
            ldsm4t(q0, q1, q2, q3, bAddr1 + off);
            mma16816(acc[0], a0, a1, a2, a3, p0, p1);
            mma16816(acc[1], a0, a1, a2, a3, p2, p3);
            mma16816(acc[2], a0, a1, a2, a3, q0, q1);
            mma16816(acc[3], a0, a1, a2, a3, q2, q3);
        }
        __syncthreads();
    }

    // cov correction + squared off-diagonal contribution
    int vc = v * C_CLASSES + c;
    const float* mrow = &g_mean[vc * D_DIM];
    int g  = lane >> 2;       // 0..7
    int tg = lane & 3;        // 0..3
    float fn = (float)n;
    float inv_nm1 = 1.f / (fn - 1.f);
    float wgt_tile = (ti == tj) ? 1.f : 2.f;
    float mi0 = mrow[ti * 64 + m0 + g];
    float mi1 = mrow[ti * 64 + m0 + g + 8];
    int gi0 = ti * 64 + m0 + g;
    int gi1 = gi0 + 8;
    float contrib = 0.f;
    #pragma unroll
    for (int nt = 0; nt < 4; nt++) {
        int n0 = nh + nt * 8;
        int gj0 = tj * 64 + n0 + 2 * tg;
        float mj0 = mrow[tj * 64 + n0 + 2 * tg];
        float mj1 = mrow[tj * 64 + n0 + 2 * tg + 1];
        float cv;
        cv = (acc[nt][0] - fn * mi0 * mj0) * inv_nm1;
        contrib += ((gi0 == gj0)     ? 0.f : wgt_tile) * cv * cv;
        cv = (acc[nt][1] - fn * mi0 * mj1) * inv_nm1;
        contrib += ((gi0 == gj0 + 1) ? 0.f : wgt_tile) * cv * cv;
        cv = (acc[nt][2] - fn * mi1 * mj0) * inv_nm1;
        contrib += ((gi1 == gj0)     ? 0.f : wgt_tile) * cv * cv;
        cv = (acc[nt][3] - fn * mi1 * mj1) * inv_nm1;
        contrib += ((gi1 == gj0 + 1) ? 0.f : wgt_tile) * cv * cv;
    }
    contrib = block_reduce_256(contrib, red);
    if (tid == 0)
        g_cov_partial[vc * N_TILES + t] = contrib;
}

// ---------------- K6: finalize all terms ------------------------------------
__global__ void k6_final(float* __restrict__ out, int N) {
    __shared__ float m[C_CLASSES * D_DIM];
    __shared__ float red[256];
    int tid = threadIdx.x;

    for (int e = tid; e < C_CLASSES * D_DIM; e += 256)
        m[e] = 0.5f * (g_mean[e] + g_mean[C_CLASSES * D_DIM + e]);

    // invariance (256 partials)
    float inv_sum = block_reduce_256(g_inv_partial[tid], red);

    // variance
    float vsum = 0.f;
    for (int e = tid; e < 2 * C_CLASSES * D_DIM; e += 256) {
        float vv = g_var[e];
        vsum += fmaxf(0.f, 1.f - sqrtf(vv + EPS_V));
    }
    vsum = block_reduce_256(vsum, red);

    // covariance
    float csum = 0.f;
    for (int e = tid; e < 2 * C_CLASSES * N_TILES; e += 256)
        csum += g_cov_partial[e];
    csum = block_reduce_256(csum, red);

    // class-discriminative margin (120 pairs)
    float psum = 0.f;
    const int npairs = C_CLASSES * (C_CLASSES - 1) / 2;
    if (tid < npairs) {
        int i = 0, rem = tid;
        while (rem >= C_CLASSES - 1 - i) { rem -= C_CLASSES - 1 - i; i++; }
        int j = i + 1 + rem;
        float d2 = 0.f;
        for (int d = 0; d < D_DIM; d++) {
            float df = m[i * D_DIM + d] - m[j * D_DIM + d];
            d2 += df * df;
        }
        float dist = sqrtf(d2);
        float rr = fmaxf(0.f, ALPHA - dist);
        psum = rr * rr;
    }
    psum = block_reduce_256(psum, red);

    if (tid == 0) {
        float inv_loss   = inv_sum / ((float)N * (float)D_DIM);
        float var_loss   = vsum * 0.5f / ((float)C_CLASSES * (float)D_DIM);
        float cov_loss   = csum * 0.5f / ((float)C_CLASSES * (float)D_DIM);
        float class_loss = psum / (float)npairs;
        out[0] = LAM * inv_loss + MU * var_loss + NU * cov_loss + ALPHA * class_loss;
    }
}

// ---------------- launch -----------------------------------------------------
extern "C" void kernel_launch(void* const* d_in, const int* in_sizes, int n_in,
                              void* d_out, int out_size) {
    const float* za     = (const float*)d_in[0];
    const float* zb     = (const float*)d_in[1];
    const int*   labels = (const int*)d_in[2];
    int N = in_sizes[2];   // labels element count

    k0_zero<<<1, 32>>>();
    k1_hist<<<32, 256>>>(labels, N);
    k2_prefix<<<1, 32>>>();
    k1b_cvt<<<256, 256>>>(za, zb, labels, N);
    k4_stats<<<dim3(C_CLASSES, 2, K4_CH), 128>>>();
    k4b_meanvar<<<32, 256>>>();
    k5_gram<<<dim3(N_TILES, C_CLASSES, 2), 256>>>();
    k6_final<<<1, 256>>>((float*)d_out, N);
}

// round 6
// speedup vs baseline: 1.4041x; 1.0118x over previous
#include <cuda_runtime.h>
#include <cuda_bf16.h>
#include <math.h>

// Problem constants (fixed by the benchmark's setup_inputs)
#define C_CLASSES 16
#define D_DIM     256
#define N_MAX     32768
#define N_TILES   10          // upper-triangle 64x64 tiles of a 256x256 gram
#define LAM   25.0f
#define MU    25.0f
#define NU     1.0f
#define ALPHA 50.0f
#define EPS_V  1e-4f

#define K4_CH 16              // k4 row-chunk splits per (class,view)
#define HIST_BLOCKS 32
#define CVT_BLOCKS 1024

// ---------------- scratch (device globals; no allocation allowed) ----------
__device__ int   g_hist_part[HIST_BLOCKS][C_CLASSES];
__device__ int   g_counts[C_CLASSES];
__device__ int   g_offsets[C_CLASSES];
__device__ int   g_cursor[C_CLASSES];
__device__ float g_sp[K4_CH][2][C_CLASSES][D_DIM];  // chunked partial sums
__device__ float g_qp[K4_CH][2][C_CLASSES][D_DIM];  // chunked partial sumsq
__device__ float g_mean[2 * C_CLASSES * D_DIM];     // [view][class][d]
__device__ float g_var [2 * C_CLASSES * D_DIM];
__device__ float g_inv_partial[CVT_BLOCKS];
__device__ float g_cov_partial[2 * C_CLASSES * N_TILES];
__device__ __nv_bfloat16 g_xa[N_MAX * D_DIM];       // class-sorted bf16 rows
__device__ __nv_bfloat16 g_xb[N_MAX * D_DIM];

// ---------------- helpers ---------------------------------------------------
__device__ __forceinline__ float block_reduce_256(float v, float* red) {
    int tid = threadIdx.x;
    red[tid] = v;
    __syncthreads();
    #pragma unroll
    for (int s = 128; s > 0; s >>= 1) {
        if (tid < s) red[tid] += red[tid + s];
        __syncthreads();
    }
    float r = red[0];
    __syncthreads();
    return r;
}

__device__ __forceinline__ void ldsm4t(unsigned& r0, unsigned& r1,
                                       unsigned& r2, unsigned& r3,
                                       unsigned addr) {
    asm volatile("ldmatrix.sync.aligned.m8n8.x4.trans.shared.b16 {%0,%1,%2,%3}, [%4];\n"
                 : "=r"(r0), "=r"(r1), "=r"(r2), "=r"(r3) : "r"(addr));
}

__device__ __forceinline__ void mma16816(float* c, unsigned a0, unsigned a1,
                                         unsigned a2, unsigned a3,
                                         unsigned b0, unsigned b1) {
    asm volatile("mma.sync.aligned.m16n8k16.row.col.f32.bf16.bf16.f32 "
                 "{%0,%1,%2,%3}, {%4,%5,%6,%7}, {%8,%9}, {%0,%1,%2,%3};\n"
                 : "+f"(c[0]), "+f"(c[1]), "+f"(c[2]), "+f"(c[3])
                 : "r"(a0), "r"(a1), "r"(a2), "r"(a3), "r"(b0), "r"(b1));
}

__device__ __forceinline__ void cpa16(void* dst, const void* src, bool pred) {
    unsigned d = (unsigned)__cvta_generic_to_shared(dst);
    int sz = pred ? 16 : 0;
    asm volatile("cp.async.cg.shared.global [%0], [%1], 16, %2;\n"
                 :: "r"(d), "l"(src), "r"(sz));
}
__device__ __forceinline__ void cpa_commit() {
    asm volatile("cp.async.commit_group;\n");
}
__device__ __forceinline__ void cpa_wait1() {
    asm volatile("cp.async.wait_group 1;\n");
}

__device__ __forceinline__ unsigned pack_bf162(float x, float y) {
    __nv_bfloat162 h = __floats2bfloat162_rn(x, y);
    return *reinterpret_cast<unsigned*>(&h);
}

// ---------------- K1: labels histogram -> per-block partials ---------------
__global__ void k1_hist(const int* __restrict__ labels, int N) {
    __shared__ int h[C_CLASSES];
    int tid = threadIdx.x;
    if (tid < C_CLASSES) h[tid] = 0;
    __syncthreads();
    for (int r = blockIdx.x * 256 + tid; r < N; r += gridDim.x * 256)
        atomicAdd(&h[labels[r]], 1);
    __syncthreads();
    if (tid < C_CLASSES) g_hist_part[blockIdx.x][tid] = h[tid];
}

// ---------------- K2: reduce partials + prefix ------------------------------
__global__ void k2_prefix() {
    int t = threadIdx.x;
    if (t < C_CLASSES) {
        int s = 0;
        #pragma unroll
        for (int b = 0; b < HIST_BLOCKS; b++) s += g_hist_part[b][t];
        g_counts[t] = s;
    }
    __syncwarp();
    if (t == 0) {
        int o = 0;
        for (int c = 0; c < C_CLASSES; c++) {
            g_offsets[c] = o;
            g_cursor[c]  = o;
            o += g_counts[c];
        }
    }
}

// ---------------- K1b: convert + class-sorted scatter + invariance ----------
// One warp per row: 32 lanes x 2 float4 per view; bf16 row written contiguously
// to its class-sorted position (rank from atomic cursor).
__global__ void __launch_bounds__(256) k1b_cvt(const float* __restrict__ za,
                                               const float* __restrict__ zb,
                                               const int* __restrict__ labels,
                                               int N) {
    __shared__ float red[256];
    int tid  = threadIdx.x;
    int lane = tid & 31;
    int warp = tid >> 5;
    int gw = blockIdx.x * 8 + warp;
    int nw = gridDim.x * 8;

    float s = 0.f;
    for (int r = gw; r < N; r += nw) {
        int pos = 0;
        if (lane == 0) pos = atomicAdd(&g_cursor[labels[r]], 1);
        pos = __shfl_sync(0xffffffffu, pos, 0);

        const float4* pa = (const float4*)(za + (long)r * D_DIM);
        const float4* pb = (const float4*)(zb + (long)r * D_DIM);
        float4 a0 = pa[lane * 2], a1 = pa[lane * 2 + 1];
        float4 b0 = pb[lane * 2], b1 = pb[lane * 2 + 1];

        float dx = a0.x - b0.x, dy = a0.y - b0.y, dz = a0.z - b0.z, dw = a0.w - b0.w;
        s += dx * dx + dy * dy + dz * dz + dw * dw;
        dx = a1.x - b1.x; dy = a1.y - b1.y; dz = a1.z - b1.z; dw = a1.w - b1.w;
        s += dx * dx + dy * dy + dz * dz + dw * dw;

        uint4 wa, wb;
        wa.x = pack_bf162(a0.x, a0.y); wa.y = pack_bf162(a0.z, a0.w);
        wa.z = pack_bf162(a1.x, a1.y); wa.w = pack_bf162(a1.z, a1.w);
        wb.x = pack_bf162(b0.x, b0.y); wb.y = pack_bf162(b0.z, b0.w);
        wb.z = pack_bf162(b1.x, b1.y); wb.w = pack_bf162(b1.z, b1.w);
        ((uint4*)(g_xa + (long)pos * D_DIM))[lane] = wa;
        ((uint4*)(g_xb + (long)pos * D_DIM))[lane] = wb;
    }
    s = block_reduce_256(s, red);
    if (tid == 0) g_inv_partial[blockIdx.x] = s;
}

// ---------------- K4: streaming per-class partial sums (bf16, L2) -----------
__global__ void __launch_bounds__(128) k4_stats() {
    int c = blockIdx.x, v = blockIdx.y, ch = blockIdx.z;
    const __nv_bfloat16* __restrict__ x = v ? g_xb : g_xa;
    int n    = g_counts[c];
    int base = g_offsets[c];
    int per  = (n + K4_CH - 1) / K4_CH;
    int lo = ch * per;
    int hi = min(n, lo + per);
    int t = threadIdx.x;                 // 0..127 -> dims 2t, 2t+1
    float s0 = 0.f, s1 = 0.f, q0 = 0.f, q1 = 0.f;
    const __nv_bfloat162* __restrict__ xp =
        (const __nv_bfloat162*)(x + (long)base * D_DIM) + t;
    int i = lo;
    #pragma unroll 8
    for (; i < hi; i++) {
        __nv_bfloat162 h = xp[(long)i * (D_DIM / 2)];
        float v0 = __bfloat162float(h.x);
        float v1 = __bfloat162float(h.y);
        s0 += v0; q0 += v0 * v0;
        s1 += v1; q1 += v1 * v1;
    }
    g_sp[ch][v][c][2 * t]     = s0;
    g_sp[ch][v][c][2 * t + 1] = s1;
    g_qp[ch][v][c][2 * t]     = q0;
    g_qp[ch][v][c][2 * t + 1] = q1;
}

// ---------------- K4b: reduce partials -> mean/var --------------------------
__global__ void k4b_meanvar() {
    int o = blockIdx.x * 256 + threadIdx.x;   // grid 32 -> 8192 entries
    int d = o & (D_DIM - 1);
    int c = (o >> 8) & (C_CLASSES - 1);
    int v = o >> 12;
    float s = 0.f, q = 0.f;
    #pragma unroll
    for (int ch = 0; ch < K4_CH; ch++) {
        s += g_sp[ch][v][c][d];
        q += g_qp[ch][v][c][d];
    }
    float fn = (float)g_counts[c];
    float m = s / fn;
    g_mean[o] = m;
    g_var[o]  = (q - fn * m * m) / (fn - 1.f);
}

// ---------------- K5: bf16 tensor-core gram, contiguous rows, cp.async ------
// Block = (tile 0..9, class, view). 64x64 tile, 8 warps, mma.m16n8k16 bf16.
// Diagonal tiles (ti==tj) reuse the A strip for B: no B loads, B ldmatrix
// addresses point into As.
__constant__ int c_ti[N_TILES] = {0,0,0,0,1,1,1,2,2,3};
__constant__ int c_tj[N_TILES] = {0,1,2,3,1,2,3,2,3,3};

#define KCHUNK 64

__global__ void __launch_bounds__(256) k5_gram() {
    int t = blockIdx.x;
    int c = blockIdx.y;
    int v = blockIdx.z;
    const __nv_bfloat16* __restrict__ x = v ? g_xb : g_xa;
    int ti = c_ti[t], tj = c_tj[t];
    bool diag = (ti == tj);

    __shared__ __nv_bfloat16 As[2][KCHUNK][72];
    __shared__ __nv_bfloat16 Bs[2][KCHUNK][72];
    __shared__ float red[256];

    int n    = g_counts[c];
    int base = g_offsets[c];
    int tid  = threadIdx.x;
    int lane = tid & 31;
    int warp = tid >> 5;

    int m0 = (warp >> 1) * 16;     // warp's m-block within 64
    int nh = (warp & 1) * 32;      // warp's n-half within 64

    unsigned aBase = (unsigned)__cvta_generic_to_shared(&As[0][0][0]);
    unsigned bBase = diag ? aBase
                          : (unsigned)__cvta_generic_to_shared(&Bs[0][0][0]);
    const unsigned STAGE = KCHUNK * 72 * 2;   // bytes per stage
    int a_row = (lane & 7) + ((lane >> 4) & 1) * 8;          // k within 16
    int a_col = m0 + ((lane >> 3) & 1) * 8;                  // m
    unsigned aAddr = aBase + (unsigned)(a_row * 72 + a_col) * 2u;
    int b_row = (lane & 7) + ((lane >> 3) & 1) * 8;          // k within 16
    int b_col = nh + ((lane >> 4) & 1) * 8;                  // n
    unsigned bAddr0 = bBase + (unsigned)(b_row * 72 + b_col) * 2u;
    unsigned bAddr1 = bAddr0 + 16u * 2u;                     // n-tiles +16

    // staging: thread covers rows kr0 and kr0+32, one 16B segment each
    int kr0 = tid >> 3;    // 0..31
    int seg = tid & 7;     // 0..7

    int nchunks = (n + KCHUNK - 1) / KCHUNK;

    #define ISSUE(ci, s) do {                                              \
        int _c0 = (ci) * KCHUNK;                                           \
        _Pragma("unroll")                                                  \
        for (int u = 0; u < 2; u++) {                                      \
            int kr = kr0 + u * 32;                                         \
            int kk = _c0 + kr;                                             \
            bool pv = kk < n;                                              \
            const __nv_bfloat16* rp = x + (long)(base + kk) * D_DIM;       \
            cpa16(&As[s][kr][seg * 8], rp + ti * 64 + seg * 8, pv);        \
            if (!diag)                                                     \
                cpa16(&Bs[s][kr][seg * 8], rp + tj * 64 + seg * 8, pv);    \
        }                                                                  \
    } while (0)

    float acc[4][4] = {};  // [n-tile 0..3][c0..c3]

    ISSUE(0, 0);
    cpa_commit();
    for (int ci = 0; ci < nchunks; ci++) {
        if (ci + 1 < nchunks) ISSUE(ci + 1, (ci + 1) & 1);
        cpa_commit();
        cpa_wait1();
        __syncthreads();
        unsigned sOff = (unsigned)(ci & 1) * STAGE;
        #pragma unroll
        for (int ks = 0; ks < KCHUNK; ks += 16) {
            unsigned off = sOff + (unsigned)(ks * 72) * 2u;
            unsigned a0, a1, a2, a3;
            unsigned p0, p1, p2, p3;
            unsigned q0, q1, q2, q3;
            ldsm4t(a0, a1, a2, a3, aAddr + off);
            ldsm4t(p0, p1, p2, p3, bAddr0 + off);
            ldsm4t(q0, q1, q2, q3, bAddr1 + off);
            mma16816(acc[0], a0, a1, a2, a3, p0, p1);
            mma16816(acc[1], a0, a1, a2, a3, p2, p3);
            mma16816(acc[2], a0, a1, a2, a3, q0, q1);
            mma16816(acc[3], a0, a1, a2, a3, q2, q3);
        }
        __syncthreads();
    }

    // cov correction + squared off-diagonal contribution
    int vc = v * C_CLASSES + c;
    const float* mrow = &g_mean[vc * D_DIM];
    int g  = lane >> 2;       // 0..7
    int tg = lane & 3;        // 0..3
    float fn = (float)n;
    float inv_nm1 = 1.f / (fn - 1.f);
    float wgt_tile = diag ? 1.f : 2.f;
    float mi0 = mrow[ti * 64 + m0 + g];
    float mi1 = mrow[ti * 64 + m0 + g + 8];
    int gi0 = ti * 64 + m0 + g;
    int gi1 = gi0 + 8;
    float contrib = 0.f;
    #pragma unroll
    for (int nt = 0; nt < 4; nt++) {
        int n0 = nh + nt * 8;
        int gj0 = tj * 64 + n0 + 2 * tg;
        float mj0 = mrow[tj * 64 + n0 + 2 * tg];
        float mj1 = mrow[tj * 64 + n0 + 2 * tg + 1];
        float cv;
        cv = (acc[nt][0] - fn * mi0 * mj0) * inv_nm1;
        contrib += ((gi0 == gj0)     ? 0.f : wgt_tile) * cv * cv;
        cv = (acc[nt][1] - fn * mi0 * mj1) * inv_nm1;
        contrib += ((gi0 == gj0 + 1) ? 0.f : wgt_tile) * cv * cv;
        cv = (acc[nt][2] - fn * mi1 * mj0) * inv_nm1;
        contrib += ((gi1 == gj0)     ? 0.f : wgt_tile) * cv * cv;
        cv = (acc[nt][3] - fn * mi1 * mj1) * inv_nm1;
        contrib += ((gi1 == gj0 + 1) ? 0.f : wgt_tile) * cv * cv;
    }
    contrib = block_reduce_256(contrib, red);
    if (tid == 0)
        g_cov_partial[vc * N_TILES + t] = contrib;
}

// ---------------- K6: finalize all terms ------------------------------------
__global__ void k6_final(float* __restrict__ out, int N) {
    __shared__ float m[C_CLASSES * D_DIM];
    __shared__ float red[256];
    int tid = threadIdx.x;

    for (int e = tid; e < C_CLASSES * D_DIM; e += 256)
        m[e] = 0.5f * (g_mean[e] + g_mean[C_CLASSES * D_DIM + e]);

    // invariance partials
    float inv_sum = 0.f;
    for (int e = tid; e < CVT_BLOCKS; e += 256) inv_sum += g_inv_partial[e];
    inv_sum = block_reduce_256(inv_sum, red);

    // variance
    float vsum = 0.f;
    for (int e = tid; e < 2 * C_CLASSES * D_DIM; e += 256) {
        float vv = g_var[e];
        vsum += fmaxf(0.f, 1.f - sqrtf(vv + EPS_V));
    }
    vsum = block_reduce_256(vsum, red);

    // covariance
    float csum = 0.f;
    for (int e = tid; e < 2 * C_CLASSES * N_TILES; e += 256)
        csum += g_cov_partial[e];
    csum = block_reduce_256(csum, red);

    // class-discriminative margin (120 pairs)
    float psum = 0.f;
    const int npairs = C_CLASSES * (C_CLASSES - 1) / 2;
    if (tid < npairs) {
        int i = 0, rem = tid;
        while (rem >= C_CLASSES - 1 - i) { rem -= C_CLASSES - 1 - i; i++; }
        int j = i + 1 + rem;
        float d2 = 0.f;
        for (int d = 0; d < D_DIM; d++) {
            float df = m[i * D_DIM + d] - m[j * D_DIM + d];
            d2 += df * df;
        }
        float dist = sqrtf(d2);
        float rr = fmaxf(0.f, ALPHA - dist);
        psum = rr * rr;
    }
    psum = block_reduce_256(psum, red);

    if (tid == 0) {
        float inv_loss   = inv_sum / ((float)N * (float)D_DIM);
        float var_loss   = vsum * 0.5f / ((float)C_CLASSES * (float)D_DIM);
        float cov_loss   = csum * 0.5f / ((float)C_CLASSES * (float)D_DIM);
        float class_loss = psum / (float)npairs;
        out[0] = LAM * inv_loss + MU * var_loss + NU * cov_loss + ALPHA * class_loss;
    }
}

// ---------------- launch -----------------------------------------------------
extern "C" void kernel_launch(void* const* d_in, const int* in_sizes, int n_in,
                              void* d_out, int out_size) {
    const float* za     = (const float*)d_in[0];
    const float* zb     = (const float*)d_in[1];
    const int*   labels = (const int*)d_in[2];
    int N = in_sizes[2];   // labels element count

    k1_hist<<<HIST_BLOCKS, 256>>>(labels, N);
    k2_prefix<<<1, 32>>>();
    k1b_cvt<<<CVT_BLOCKS, 256>>>(za, zb, labels, N);
    k4_stats<<<dim3(C_CLASSES, 2, K4_CH), 128>>>();
    k4b_meanvar<<<32, 256>>>();
    k5_gram<<<dim3(N_TILES, C_CLASSES, 2), 256>>>();
    k6_final<<<1, 256>>>((float*)d_out, N);
}

// round 7
// speedup vs baseline: 1.5233x; 1.0849x over previous
#include <cuda_runtime.h>
#include <cuda_bf16.h>
#include <math.h>

// Problem constants (fixed by the benchmark's setup_inputs)
#define C_CLASSES 16
#define D_DIM     256
#define N_MAX     32768
#define N_TILES   10          // upper-triangle 64x64 tiles of a 256x256 gram
#define LAM   25.0f
#define MU    25.0f
#define NU     1.0f
#define ALPHA 50.0f
#define EPS_V  1e-4f

#define HIST_BLOCKS 32
#define CVT_BLOCKS 1024

// ---------------- scratch (device globals; no allocation allowed) ----------
__device__ int   g_hist_part[HIST_BLOCKS][C_CLASSES];
__device__ int   g_counts[C_CLASSES];
__device__ int   g_offsets[C_CLASSES];
__device__ int   g_cursor[C_CLASSES];
__device__ float g_mean[2 * C_CLASSES * D_DIM];     // [view][class][d]
__device__ float g_var [2 * C_CLASSES * D_DIM];
__device__ float g_colsum[2][C_CLASSES][D_DIM];     // written by diag blocks
__device__ float g_gram[2][C_CLASSES][N_TILES][64 * 64];  // raw gram tiles
__device__ float g_inv_partial[CVT_BLOCKS];
__device__ float g_cov_partial[2 * C_CLASSES * N_TILES];
__device__ __nv_bfloat16 g_xa[N_MAX * D_DIM];       // class-sorted bf16 rows
__device__ __nv_bfloat16 g_xb[N_MAX * D_DIM];

// ---------------- helpers ---------------------------------------------------
__device__ __forceinline__ float block_reduce_256(float v, float* red) {
    int tid = threadIdx.x;
    red[tid] = v;
    __syncthreads();
    #pragma unroll
    for (int s = 128; s > 0; s >>= 1) {
        if (tid < s) red[tid] += red[tid + s];
        __syncthreads();
    }
    float r = red[0];
    __syncthreads();
    return r;
}

__device__ __forceinline__ void ldsm4t(unsigned& r0, unsigned& r1,
                                       unsigned& r2, unsigned& r3,
                                       unsigned addr) {
    asm volatile("ldmatrix.sync.aligned.m8n8.x4.trans.shared.b16 {%0,%1,%2,%3}, [%4];\n"
                 : "=r"(r0), "=r"(r1), "=r"(r2), "=r"(r3) : "r"(addr));
}

__device__ __forceinline__ void mma16816(float* c, unsigned a0, unsigned a1,
                                         unsigned a2, unsigned a3,
                                         unsigned b0, unsigned b1) {
    asm volatile("mma.sync.aligned.m16n8k16.row.col.f32.bf16.bf16.f32 "
                 "{%0,%1,%2,%3}, {%4,%5,%6,%7}, {%8,%9}, {%0,%1,%2,%3};\n"
                 : "+f"(c[0]), "+f"(c[1]), "+f"(c[2]), "+f"(c[3])
                 : "r"(a0), "r"(a1), "r"(a2), "r"(a3), "r"(b0), "r"(b1));
}

__device__ __forceinline__ void cpa16(void* dst, const void* src, bool pred) {
    unsigned d = (unsigned)__cvta_generic_to_shared(dst);
    int sz = pred ? 16 : 0;
    asm volatile("cp.async.cg.shared.global [%0], [%1], 16, %2;\n"
                 :: "r"(d), "l"(src), "r"(sz));
}
__device__ __forceinline__ void cpa_commit() {
    asm volatile("cp.async.commit_group;\n");
}
__device__ __forceinline__ void cpa_wait1() {
    asm volatile("cp.async.wait_group 1;\n");
}

__device__ __forceinline__ unsigned pack_bf162(float x, float y) {
    __nv_bfloat162 h = __floats2bfloat162_rn(x, y);
    return *reinterpret_cast<unsigned*>(&h);
}

// ---------------- K1: labels histogram -> per-block partials ---------------
__global__ void k1_hist(const int* __restrict__ labels, int N) {
    __shared__ int h[C_CLASSES];
    int tid = threadIdx.x;
    if (tid < C_CLASSES) h[tid] = 0;
    __syncthreads();
    for (int r = blockIdx.x * 256 + tid; r < N; r += gridDim.x * 256)
        atomicAdd(&h[labels[r]], 1);
    __syncthreads();
    if (tid < C_CLASSES) g_hist_part[blockIdx.x][tid] = h[tid];
}

// ---------------- K2: reduce partials + prefix ------------------------------
__global__ void k2_prefix() {
    int t = threadIdx.x;
    if (t < C_CLASSES) {
        int s = 0;
        #pragma unroll
        for (int b = 0; b < HIST_BLOCKS; b++) s += g_hist_part[b][t];
        g_counts[t] = s;
    }
    __syncwarp();
    if (t == 0) {
        int o = 0;
        for (int c = 0; c < C_CLASSES; c++) {
            g_offsets[c] = o;
            g_cursor[c]  = o;
            o += g_counts[c];
        }
    }
}

// ---------------- K1b: convert + class-sorted scatter + invariance ----------
__global__ void __launch_bounds__(256) k1b_cvt(const float* __restrict__ za,
                                               const float* __restrict__ zb,
                                               const int* __restrict__ labels,
                                               int N) {
    __shared__ float red[256];
    int tid  = threadIdx.x;
    int lane = tid & 31;
    int warp = tid >> 5;
    int gw = blockIdx.x * 8 + warp;
    int nw = gridDim.x * 8;

    float s = 0.f;
    for (int r = gw; r < N; r += nw) {
        int pos = 0;
        if (lane == 0) pos = atomicAdd(&g_cursor[labels[r]], 1);
        pos = __shfl_sync(0xffffffffu, pos, 0);

        const float4* pa = (const float4*)(za + (long)r * D_DIM);
        const float4* pb = (const float4*)(zb + (long)r * D_DIM);
        float4 a0 = pa[lane * 2], a1 = pa[lane * 2 + 1];
        float4 b0 = pb[lane * 2], b1 = pb[lane * 2 + 1];

        float dx = a0.x - b0.x, dy = a0.y - b0.y, dz = a0.z - b0.z, dw = a0.w - b0.w;
        s += dx * dx + dy * dy + dz * dz + dw * dw;
        dx = a1.x - b1.x; dy = a1.y - b1.y; dz = a1.z - b1.z; dw = a1.w - b1.w;
        s += dx * dx + dy * dy + dz * dz + dw * dw;

        uint4 wa, wb;
        wa.x = pack_bf162(a0.x, a0.y); wa.y = pack_bf162(a0.z, a0.w);
        wa.z = pack_bf162(a1.x, a1.y); wa.w = pack_bf162(a1.z, a1.w);
        wb.x = pack_bf162(b0.x, b0.y); wb.y = pack_bf162(b0.z, b0.w);
        wb.z = pack_bf162(b1.x, b1.y); wb.w = pack_bf162(b1.z, b1.w);
        ((uint4*)(g_xa + (long)pos * D_DIM))[lane] = wa;
        ((uint4*)(g_xb + (long)pos * D_DIM))[lane] = wb;
    }
    s = block_reduce_256(s, red);
    if (tid == 0) g_inv_partial[blockIdx.x] = s;
}

// ---------------- K5: bf16 tensor-core RAW gram + colsum (ones-mma) ---------
// Block = (tile 0..9, class, view). 64x64 tile, 8 warps, mma.m16n8k16 bf16.
// Diagonal tiles reuse the A strip for B and additionally compute per-column
// sums via an all-ones A fragment (exact bf16-term sum, fp32 accum).
__constant__ int c_ti[N_TILES] = {0,0,0,0,1,1,1,2,2,3};
__constant__ int c_tj[N_TILES] = {0,1,2,3,1,2,3,2,3,3};

#define KCHUNK 64
#define ONES_BF162 0x3F803F80u

__global__ void __launch_bounds__(256) k5_gram() {
    int t = blockIdx.x;
    int c = blockIdx.y;
    int v = blockIdx.z;
    const __nv_bfloat16* __restrict__ x = v ? g_xb : g_xa;
    int ti = c_ti[t], tj = c_tj[t];
    bool diag = (ti == tj);

    __shared__ __nv_bfloat16 As[2][KCHUNK][72];
    __shared__ __nv_bfloat16 Bs[2][KCHUNK][72];

    int n    = g_counts[c];
    int base = g_offsets[c];
    int tid  = threadIdx.x;
    int lane = tid & 31;
    int warp = tid >> 5;

    int m0 = (warp >> 1) * 16;     // warp's m-block within 64
    int nh = (warp & 1) * 32;      // warp's n-half within 64
    bool do_sum = diag && (warp < 2);   // warps 0,1 compute colsums

    unsigned aBase = (unsigned)__cvta_generic_to_shared(&As[0][0][0]);
    unsigned bBase = diag ? aBase
                          : (unsigned)__cvta_generic_to_shared(&Bs[0][0][0]);
    const unsigned STAGE = KCHUNK * 72 * 2;   // bytes per stage
    int a_row = (lane & 7) + ((lane >> 4) & 1) * 8;          // k within 16
    int a_col = m0 + ((lane >> 3) & 1) * 8;                  // m
    unsigned aAddr = aBase + (unsigned)(a_row * 72 + a_col) * 2u;
    int b_row = (lane & 7) + ((lane >> 3) & 1) * 8;          // k within 16
    int b_col = nh + ((lane >> 4) & 1) * 8;                  // n
    unsigned bAddr0 = bBase + (unsigned)(b_row * 72 + b_col) * 2u;
    unsigned bAddr1 = bAddr0 + 16u * 2u;                     // n-tiles +16

    // staging: thread covers rows kr0 and kr0+32, one 16B segment each
    int kr0 = tid >> 3;    // 0..31
    int seg = tid & 7;     // 0..7

    int nchunks = (n + KCHUNK - 1) / KCHUNK;

    #define ISSUE(ci, s) do {                                              \
        int _c0 = (ci) * KCHUNK;                                           \
        _Pragma("unroll")                                                  \
        for (int u = 0; u < 2; u++) {                                      \
            int kr = kr0 + u * 32;                                         \
            int kk = _c0 + kr;                                             \
            bool pv = kk < n;                                              \
            const __nv_bfloat16* rp = x + (long)(base + kk) * D_DIM;       \
            cpa16(&As[s][kr][seg * 8], rp + ti * 64 + seg * 8, pv);        \
            if (!diag)                                                     \
                cpa16(&Bs[s][kr][seg * 8], rp + tj * 64 + seg * 8, pv);    \
        }                                                                  \
    } while (0)

    float acc[4][4] = {};    // [n-tile 0..3][c0..c3]
    float accS[4][4] = {};   // colsum accumulators (diag, warps 0-1)

    ISSUE(0, 0);
    cpa_commit();
    for (int ci = 0; ci < nchunks; ci++) {
        if (ci + 1 < nchunks) ISSUE(ci + 1, (ci + 1) & 1);
        cpa_commit();
        cpa_wait1();
        __syncthreads();
        unsigned sOff = (unsigned)(ci & 1) * STAGE;
        #pragma unroll
        for (int ks = 0; ks < KCHUNK; ks += 16) {
            unsigned off = sOff + (unsigned)(ks * 72) * 2u;
            unsigned a0, a1, a2, a3;
            unsigned p0, p1, p2, p3;
            unsigned q0, q1, q2, q3;
            ldsm4t(a0, a1, a2, a3, aAddr + off);
            ldsm4t(p0, p1, p2, p3, bAddr0 + off);
            ldsm4t(q0, q1, q2, q3, bAddr1 + off);
            mma16816(acc[0], a0, a1, a2, a3, p0, p1);
            mma16816(acc[1], a0, a1, a2, a3, p2, p3);
            mma16816(acc[2], a0, a1, a2, a3, q0, q1);
            mma16816(acc[3], a0, a1, a2, a3, q2, q3);
            if (do_sum) {
                mma16816(accS[0], ONES_BF162, ONES_BF162, ONES_BF162, ONES_BF162, p0, p1);
                mma16816(accS[1], ONES_BF162, ONES_BF162, ONES_BF162, ONES_BF162, p2, p3);
                mma16816(accS[2], ONES_BF162, ONES_BF162, ONES_BF162, ONES_BF162, q0, q1);
                mma16816(accS[3], ONES_BF162, ONES_BF162, ONES_BF162, ONES_BF162, q2, q3);
            }
        }
        __syncthreads();
    }

    // ---- write raw gram tile ----
    float* G = g_gram[v][c][t];
    int g  = lane >> 2;       // 0..7
    int tg = lane & 3;        // 0..3
    int r0 = m0 + g, r1 = m0 + g + 8;
    #pragma unroll
    for (int nt = 0; nt < 4; nt++) {
        int col = nh + nt * 8 + 2 * tg;
        *(float2*)&G[r0 * 64 + col] = make_float2(acc[nt][0], acc[nt][1]);
        *(float2*)&G[r1 * 64 + col] = make_float2(acc[nt][2], acc[nt][3]);
    }

    // ---- diag blocks: write colsums (row 0 of ones-mma result) ----
    if (do_sum && g == 0) {   // lanes 0..3
        #pragma unroll
        for (int nt = 0; nt < 4; nt++) {
            int col = nh + nt * 8 + 2 * tg;
            g_colsum[v][c][ti * 64 + col]     = accS[nt][0];
            g_colsum[v][c][ti * 64 + col + 1] = accS[nt][1];
        }
    }
}

// ---------------- K5b: mean/var from colsum + gram diagonal -----------------
__constant__ int c_diagt[4] = {0, 4, 7, 9};

__global__ void k5b_meanvar() {
    int o = blockIdx.x * 256 + threadIdx.x;   // grid 32 -> 8192 entries
    int d = o & (D_DIM - 1);
    int c = (o >> 8) & (C_CLASSES - 1);
    int v = o >> 12;
    float fn = (float)g_counts[c];
    float m = g_colsum[v][c][d] / fn;
    g_mean[o] = m;
    int s = d >> 6, dd = d & 63;
    float Gdd = g_gram[v][c][c_diagt[s]][dd * 64 + dd];
    g_var[o] = (Gdd - fn * m * m) / (fn - 1.f);
}

// ---------------- K5c: covariance partials from raw gram + means ------------
__global__ void __launch_bounds__(256) k5c_cov() {
    int t = blockIdx.x;
    int c = blockIdx.y;
    int v = blockIdx.z;
    int ti = c_ti[t], tj = c_tj[t];
    bool diag = (ti == tj);

    __shared__ float mi[64], mj[64];
    __shared__ float red[256];
    int tid = threadIdx.x;
    int vc = v * C_CLASSES + c;
    const float* mrow = &g_mean[vc * D_DIM];
    if (tid < 64)        mi[tid]      = mrow[ti * 64 + tid];
    else if (tid < 128)  mj[tid - 64] = mrow[tj * 64 + tid - 64];
    __syncthreads();

    const float* __restrict__ G = g_gram[v][c][t];
    float fn = (float)g_counts[c];
    float inv_nm1 = 1.f / (fn - 1.f);
    float wgt_tile = diag ? 1.f : 2.f;

    float sum = 0.f;
    #pragma unroll
    for (int k = 0; k < 16; k++) {
        int idx = tid + k * 256;
        int r = idx >> 6, col = idx & 63;
        float cv = (G[idx] - fn * mi[r] * mj[col]) * inv_nm1;
        float w = (diag && r == col) ? 0.f : wgt_tile;
        sum += w * cv * cv;
    }
    sum = block_reduce_256(sum, red);
    if (tid == 0) g_cov_partial[vc * N_TILES + t] = sum;
}

// ---------------- K6: finalize all terms ------------------------------------
__global__ void k6_final(float* __restrict__ out, int N) {
    __shared__ float m[C_CLASSES * D_DIM];
    __shared__ float red[256];
    int tid = threadIdx.x;

    for (int e = tid; e < C_CLASSES * D_DIM; e += 256)
        m[e] = 0.5f * (g_mean[e] + g_mean[C_CLASSES * D_DIM + e]);

    // invariance partials
    float inv_sum = 0.f;
    for (int e = tid; e < CVT_BLOCKS; e += 256) inv_sum += g_inv_partial[e];
    inv_sum = block_reduce_256(inv_sum, red);

    // variance
    float vsum = 0.f;
    for (int e = tid; e < 2 * C_CLASSES * D_DIM; e += 256) {
        float vv = g_var[e];
        vsum += fmaxf(0.f, 1.f - sqrtf(vv + EPS_V));
    }
    vsum = block_reduce_256(vsum, red);

    // covariance
    float csum = 0.f;
    for (int e = tid; e < 2 * C_CLASSES * N_TILES; e += 256)
        csum += g_cov_partial[e];
    csum = block_reduce_256(csum, red);

    // class-discriminative margin (120 pairs)
    float psum = 0.f;
    const int npairs = C_CLASSES * (C_CLASSES - 1) / 2;
    if (tid < npairs) {
        int i = 0, rem = tid;
        while (rem >= C_CLASSES - 1 - i) { rem -= C_CLASSES - 1 - i; i++; }
        int j = i + 1 + rem;
        float d2 = 0.f;
        for (int d = 0; d < D_DIM; d++) {
            float df = m[i * D_DIM + d] - m[j * D_DIM + d];
            d2 += df * df;
        }
        float dist = sqrtf(d2);
        float rr = fmaxf(0.f, ALPHA - dist);
        psum = rr * rr;
    }
    psum = block_reduce_256(psum, red);

    if (tid == 0) {
        float inv_loss   = inv_sum / ((float)N * (float)D_DIM);
        float var_loss   = vsum * 0.5f / ((float)C_CLASSES * (float)D_DIM);
        float cov_loss   = csum * 0.5f / ((float)C_CLASSES * (float)D_DIM);
        float class_loss = psum / (float)npairs;
        out[0] = LAM * inv_loss + MU * var_loss + NU * cov_loss + ALPHA * class_loss;
    }
}

// ---------------- launch -----------------------------------------------------
extern "C" void kernel_launch(void* const* d_in, const int* in_sizes, int n_in,
                              void* d_out, int out_size) {
    const float* za     = (const float*)d_in[0];
    const float* zb     = (const float*)d_in[1];
    const int*   labels = (const int*)d_in[2];
    int N = in_sizes[2];   // labels element count

    k1_hist<<<HIST_BLOCKS, 256>>>(labels, N);
    k2_prefix<<<1, 32>>>();
    k1b_cvt<<<CVT_BLOCKS, 256>>>(za, zb, labels, N);
    k5_gram<<<dim3(N_TILES, C_CLASSES, 2), 256>>>();
    k5b_meanvar<<<32, 256>>>();
    k5c_cov<<<dim3(N_TILES, C_CLASSES, 2), 256>>>();
    k6_final<<<1, 256>>>((float*)d_out, N);
}

// round 8
// speedup vs baseline: 1.5613x; 1.0249x over previous
#include <cuda_runtime.h>
#include <cuda_bf16.h>
#include <math.h>

// Problem constants (fixed by the benchmark's setup_inputs)
#define C_CLASSES 16
#define D_DIM     256
#define N_MAX     32768
#define N_TILES   10          // upper-triangle 64x64 tiles of a 256x256 gram
#define LAM   25.0f
#define MU    25.0f
#define NU     1.0f
#define ALPHA 50.0f
#define EPS_V  1e-4f

#define HIST_BLOCKS 32
#define CVT_BLOCKS 1024

// ---------------- scratch (device globals; no allocation allowed) ----------
__device__ int   g_hist_part[HIST_BLOCKS][C_CLASSES];
__device__ int   g_counts[C_CLASSES];
__device__ int   g_offsets[C_CLASSES];
__device__ int   g_cursor[C_CLASSES];
__device__ float g_mean[2 * C_CLASSES * D_DIM];     // [view][class][d]
__device__ float g_var [2 * C_CLASSES * D_DIM];
__device__ float g_colsum[2][C_CLASSES][D_DIM];     // written by diag blocks
__device__ float g_gram[2][C_CLASSES][N_TILES][64 * 64];  // raw gram tiles
__device__ float g_inv_partial[CVT_BLOCKS];
__device__ float g_cov_partial[2 * C_CLASSES * N_TILES];
__device__ __nv_bfloat16 g_xa[N_MAX * D_DIM];       // class-sorted bf16 rows
__device__ __nv_bfloat16 g_xb[N_MAX * D_DIM];

// ---------------- helpers ---------------------------------------------------
__device__ __forceinline__ float block_reduce_256(float v, float* red) {
    int tid = threadIdx.x;
    red[tid] = v;
    __syncthreads();
    #pragma unroll
    for (int s = 128; s > 0; s >>= 1) {
        if (tid < s) red[tid] += red[tid + s];
        __syncthreads();
    }
    float r = red[0];
    __syncthreads();
    return r;
}

__device__ __forceinline__ void ldsm4t(unsigned& r0, unsigned& r1,
                                       unsigned& r2, unsigned& r3,
                                       unsigned addr) {
    asm volatile("ldmatrix.sync.aligned.m8n8.x4.trans.shared.b16 {%0,%1,%2,%3}, [%4];\n"
                 : "=r"(r0), "=r"(r1), "=r"(r2), "=r"(r3) : "r"(addr));
}

__device__ __forceinline__ void mma16816(float* c, unsigned a0, unsigned a1,
                                         unsigned a2, unsigned a3,
                                         unsigned b0, unsigned b1) {
    asm volatile("mma.sync.aligned.m16n8k16.row.col.f32.bf16.bf16.f32 "
                 "{%0,%1,%2,%3}, {%4,%5,%6,%7}, {%8,%9}, {%0,%1,%2,%3};\n"
                 : "+f"(c[0]), "+f"(c[1]), "+f"(c[2]), "+f"(c[3])
                 : "r"(a0), "r"(a1), "r"(a2), "r"(a3), "r"(b0), "r"(b1));
}

__device__ __forceinline__ void cpa16(void* dst, const void* src, bool pred) {
    unsigned d = (unsigned)__cvta_generic_to_shared(dst);
    int sz = pred ? 16 : 0;
    asm volatile("cp.async.cg.shared.global [%0], [%1], 16, %2;\n"
                 :: "r"(d), "l"(src), "r"(sz));
}
__device__ __forceinline__ void cpa_commit() {
    asm volatile("cp.async.commit_group;\n");
}
__device__ __forceinline__ void cpa_wait2() {
    asm volatile("cp.async.wait_group 2;\n");
}

__device__ __forceinline__ unsigned pack_bf162(float x, float y) {
    __nv_bfloat162 h = __floats2bfloat162_rn(x, y);
    return *reinterpret_cast<unsigned*>(&h);
}

// ---------------- K1: labels histogram -> per-block partials ---------------
__global__ void k1_hist(const int* __restrict__ labels, int N) {
    __shared__ int h[C_CLASSES];
    int tid = threadIdx.x;
    if (tid < C_CLASSES) h[tid] = 0;
    __syncthreads();
    for (int r = blockIdx.x * 256 + tid; r < N; r += gridDim.x * 256)
        atomicAdd(&h[labels[r]], 1);
    __syncthreads();
    if (tid < C_CLASSES) g_hist_part[blockIdx.x][tid] = h[tid];
}

// ---------------- K2: reduce partials + prefix ------------------------------
__global__ void k2_prefix() {
    int t = threadIdx.x;
    if (t < C_CLASSES) {
        int s = 0;
        #pragma unroll
        for (int b = 0; b < HIST_BLOCKS; b++) s += g_hist_part[b][t];
        g_counts[t] = s;
    }
    __syncwarp();
    if (t == 0) {
        int o = 0;
        for (int c = 0; c < C_CLASSES; c++) {
            g_offsets[c] = o;
            g_cursor[c]  = o;
            o += g_counts[c];
        }
    }
}

// ---------------- K1b: convert + class-sorted scatter + invariance ----------
// fp32 inputs are read-once -> __ldcs (evict-first) keeps the bf16 corpus in L2.
__global__ void __launch_bounds__(256) k1b_cvt(const float* __restrict__ za,
                                               const float* __restrict__ zb,
                                               const int* __restrict__ labels,
                                               int N) {
    __shared__ float red[256];
    int tid  = threadIdx.x;
    int lane = tid & 31;
    int warp = tid >> 5;
    int gw = blockIdx.x * 8 + warp;
    int nw = gridDim.x * 8;

    float s = 0.f;
    for (int r = gw; r < N; r += nw) {
        int pos = 0;
        if (lane == 0) pos = atomicAdd(&g_cursor[labels[r]], 1);
        pos = __shfl_sync(0xffffffffu, pos, 0);

        const float4* pa = (const float4*)(za + (long)r * D_DIM);
        const float4* pb = (const float4*)(zb + (long)r * D_DIM);
        float4 a0 = __ldcs(pa + lane * 2), a1 = __ldcs(pa + lane * 2 + 1);
        float4 b0 = __ldcs(pb + lane * 2), b1 = __ldcs(pb + lane * 2 + 1);

        float dx = a0.x - b0.x, dy = a0.y - b0.y, dz = a0.z - b0.z, dw = a0.w - b0.w;
        s += dx * dx + dy * dy + dz * dz + dw * dw;
        dx = a1.x - b1.x; dy = a1.y - b1.y; dz = a1.z - b1.z; dw = a1.w - b1.w;
        s += dx * dx + dy * dy + dz * dz + dw * dw;

        uint4 wa, wb;
        wa.x = pack_bf162(a0.x, a0.y); wa.y = pack_bf162(a0.z, a0.w);
        wa.z = pack_bf162(a1.x, a1.y); wa.w = pack_bf162(a1.z, a1.w);
        wb.x = pack_bf162(b0.x, b0.y); wb.y = pack_bf162(b0.z, b0.w);
        wb.z = pack_bf162(b1.x, b1.y); wb.w = pack_bf162(b1.z, b1.w);
        ((uint4*)(g_xa + (long)pos * D_DIM))[lane] = wa;
        ((uint4*)(g_xb + (long)pos * D_DIM))[lane] = wb;
    }
    s = block_reduce_256(s, red);
    if (tid == 0) g_inv_partial[blockIdx.x] = s;
}

// ---------------- K5: bf16 tensor-core RAW gram + colsum (smem FADD) --------
// Block = (tile 0..9, class, view). 64x64 tile, 8 warps, mma.m16n8k16 bf16.
// KCHUNK 32, 3-stage cp.async. Diag tiles reuse A strip for B; diag blocks
// also accumulate per-column sums from smem (fp32 adds of bf16 values).
__constant__ int c_ti[N_TILES] = {0,0,0,0,1,1,1,2,2,3};
__constant__ int c_tj[N_TILES] = {0,1,2,3,1,2,3,2,3,3};

#define KCHUNK 32
#define NSTAGE 3

__global__ void __launch_bounds__(256, 4) k5_gram() {
    int t = blockIdx.x;
    int c = blockIdx.y;
    int v = blockIdx.z;
    const __nv_bfloat16* __restrict__ x = v ? g_xb : g_xa;
    int ti = c_ti[t], tj = c_tj[t];
    bool diag = (ti == tj);

    __shared__ __nv_bfloat16 As[NSTAGE][KCHUNK][72];
    __shared__ __nv_bfloat16 Bs[NSTAGE][KCHUNK][72];
    __shared__ float red[256];

    int n    = g_counts[c];
    int base = g_offsets[c];
    int tid  = threadIdx.x;
    int lane = tid & 31;
    int warp = tid >> 5;

    int m0 = (warp >> 1) * 16;     // warp's m-block within 64
    int nh = (warp & 1) * 32;      // warp's n-half within 64

    unsigned aBase = (unsigned)__cvta_generic_to_shared(&As[0][0][0]);
    unsigned bBase = diag ? aBase
                          : (unsigned)__cvta_generic_to_shared(&Bs[0][0][0]);
    const unsigned STAGE = KCHUNK * 72 * 2;   // bytes per stage
    int a_row = (lane & 7) + ((lane >> 4) & 1) * 8;          // k within 16
    int a_col = m0 + ((lane >> 3) & 1) * 8;                  // m
    unsigned aAddr = aBase + (unsigned)(a_row * 72 + a_col) * 2u;
    int b_row = (lane & 7) + ((lane >> 3) & 1) * 8;          // k within 16
    int b_col = nh + ((lane >> 4) & 1) * 8;                  // n
    unsigned bAddr0 = bBase + (unsigned)(b_row * 72 + b_col) * 2u;
    unsigned bAddr1 = bAddr0 + 16u * 2u;                     // n-tiles +16

    // staging: one 16B segment per thread (32 rows x 8 segs = 256 tasks)
    int kr  = tid >> 3;    // 0..31
    int seg = tid & 7;     // 0..7

    // colsum assignment (diag blocks): col = tid&63, rows (tid>>6)*8..+7
    int cs_col = tid & 63;
    int cs_r0  = (tid >> 6) * 8;
    float cs = 0.f;

    int nchunks = (n + KCHUNK - 1) / KCHUNK;

    #define ISSUE(ci, st) do {                                             \
        int kk = (ci) * KCHUNK + kr;                                       \
        bool pv = kk < n;                                                  \
        const __nv_bfloat16* rp = x + (long)(base + kk) * D_DIM;           \
        cpa16(&As[st][kr][seg * 8], rp + ti * 64 + seg * 8, pv);           \
        if (!diag)                                                         \
            cpa16(&Bs[st][kr][seg * 8], rp + tj * 64 + seg * 8, pv);       \
    } while (0)

    float acc[4][4] = {};    // [n-tile 0..3][c0..c3]

    ISSUE(0, 0);
    cpa_commit();
    if (nchunks > 1) ISSUE(1, 1);
    cpa_commit();
    for (int ci = 0; ci < nchunks; ci++) {
        if (ci + 2 < nchunks) {
            int st = (ci + 2) % NSTAGE;
            ISSUE(ci + 2, st);
        }
        cpa_commit();
        cpa_wait2();
        __syncthreads();
        int st = ci % NSTAGE;
        unsigned sOff = (unsigned)st * STAGE;
        #pragma unroll
        for (int ks = 0; ks < KCHUNK; ks += 16) {
            unsigned off = sOff + (unsigned)(ks * 72) * 2u;
            unsigned a0, a1, a2, a3;
            unsigned p0, p1, p2, p3;
            unsigned q0, q1, q2, q3;
            ldsm4t(a0, a1, a2, a3, aAddr + off);
            ldsm4t(p0, p1, p2, p3, bAddr0 + off);
            ldsm4t(q0, q1, q2, q3, bAddr1 + off);
            mma16816(acc[0], a0, a1, a2, a3, p0, p1);
            mma16816(acc[1], a0, a1, a2, a3, p2, p3);
            mma16816(acc[2], a0, a1, a2, a3, q0, q1);
            mma16816(acc[3], a0, a1, a2, a3, q2, q3);
        }
        if (diag) {
            #pragma unroll
            for (int u = 0; u < 8; u++)
                cs += __bfloat162float(As[st][cs_r0 + u][cs_col]);
        }
        __syncthreads();
    }

    // ---- write raw gram tile ----
    float* G = g_gram[v][c][t];
    int g  = lane >> 2;       // 0..7
    int tg = lane & 3;        // 0..3
    int r0 = m0 + g, r1 = m0 + g + 8;
    #pragma unroll
    for (int nt = 0; nt < 4; nt++) {
        int col = nh + nt * 8 + 2 * tg;
        *(float2*)&G[r0 * 64 + col] = make_float2(acc[nt][0], acc[nt][1]);
        *(float2*)&G[r1 * 64 + col] = make_float2(acc[nt][2], acc[nt][3]);
    }

    // ---- diag blocks: reduce + write colsums ----
    if (diag) {
        red[tid] = cs;
        __syncthreads();
        if (tid < 64)
            g_colsum[v][c][ti * 64 + tid] =
                red[tid] + red[tid + 64] + red[tid + 128] + red[tid + 192];
    }
}

// ---------------- K5b: mean/var from colsum + gram diagonal -----------------
__constant__ int c_diagt[4] = {0, 4, 7, 9};

__global__ void k5b_meanvar() {
    int o = blockIdx.x * 256 + threadIdx.x;   // grid 32 -> 8192 entries
    int d = o & (D_DIM - 1);
    int c = (o >> 8) & (C_CLASSES - 1);
    int v = o >> 12;
    float fn = (float)g_counts[c];
    float m = g_colsum[v][c][d] / fn;
    g_mean[o] = m;
    int s = d >> 6, dd = d & 63;
    float Gdd = g_gram[v][c][c_diagt[s]][dd * 64 + dd];
    g_var[o] = (Gdd - fn * m * m) / (fn - 1.f);
}

// ---------------- K5c: covariance partials from raw gram + means ------------
__global__ void __launch_bounds__(256) k5c_cov() {
    int t = blockIdx.x;
    int c = blockIdx.y;
    int v = blockIdx.z;
    int ti = c_ti[t], tj = c_tj[t];
    bool diag = (ti == tj);

    __shared__ float mi[64], mj[64];
    __shared__ float red[256];
    int tid = threadIdx.x;
    int vc = v * C_CLASSES + c;
    const float* mrow = &g_mean[vc * D_DIM];
    if (tid < 64)        mi[tid]      = mrow[ti * 64 + tid];
    else if (tid < 128)  mj[tid - 64] = mrow[tj * 64 + tid - 64];
    __syncthreads();

    const float* __restrict__ G = g_gram[v][c][t];
    float fn = (float)g_counts[c];
    float inv_nm1 = 1.f / (fn - 1.f);
    float wgt_tile = diag ? 1.f : 2.f;

    float sum = 0.f;
    #pragma unroll
    for (int k = 0; k < 16; k++) {
        int idx = tid + k * 256;
        int r = idx >> 6, col = idx & 63;
        float cv = (G[idx] - fn * mi[r] * mj[col]) * inv_nm1;
        float w = (diag && r == col) ? 0.f : wgt_tile;
        sum += w * cv * cv;
    }
    sum = block_reduce_256(sum, red);
    if (tid == 0) g_cov_partial[vc * N_TILES + t] = sum;
}

// ---------------- K6: finalize all terms ------------------------------------
__global__ void k6_final(float* __restrict__ out, int N) {
    __shared__ float m[C_CLASSES * D_DIM];
    __shared__ float red[256];
    int tid = threadIdx.x;

    for (int e = tid; e < C_CLASSES * D_DIM; e += 256)
        m[e] = 0.5f * (g_mean[e] + g_mean[C_CLASSES * D_DIM + e]);

    // invariance partials
    float inv_sum = 0.f;
    for (int e = tid; e < CVT_BLOCKS; e += 256) inv_sum += g_inv_partial[e];
    inv_sum = block_reduce_256(inv_sum, red);

    // variance
    float vsum = 0.f;
    for (int e = tid; e < 2 * C_CLASSES * D_DIM; e += 256) {
        float vv = g_var[e];
        vsum += fmaxf(0.f, 1.f - sqrtf(vv + EPS_V));
    }
    vsum = block_reduce_256(vsum, red);

    // covariance
    float csum = 0.f;
    for (int e = tid; e < 2 * C_CLASSES * N_TILES; e += 256)
        csum += g_cov_partial[e];
    csum = block_reduce_256(csum, red);

    // class-discriminative margin (120 pairs)
    float psum = 0.f;
    const int npairs = C_CLASSES * (C_CLASSES - 1) / 2;
    if (tid < npairs) {
        int i = 0, rem = tid;
        while (rem >= C_CLASSES - 1 - i) { rem -= C_CLASSES - 1 - i; i++; }
        int j = i + 1 + rem;
        float d2 = 0.f;
        for (int d = 0; d < D_DIM; d++) {
            float df = m[i * D_DIM + d] - m[j * D_DIM + d];
            d2 += df * df;
        }
        float dist = sqrtf(d2);
        float rr = fmaxf(0.f, ALPHA - dist);
        psum = rr * rr;
    }
    psum = block_reduce_256(psum, red);

    if (tid == 0) {
        float inv_loss   = inv_sum / ((float)N * (float)D_DIM);
        float var_loss   = vsum * 0.5f / ((float)C_CLASSES * (float)D_DIM);
        float cov_loss   = csum * 0.5f / ((float)C_CLASSES * (float)D_DIM);
        float class_loss = psum / (float)npairs;
        out[0] = LAM * inv_loss + MU * var_loss + NU * cov_loss + ALPHA * class_loss;
    }
}

// ---------------- launch -----------------------------------------------------
extern "C" void kernel_launch(void* const* d_in, const int* in_sizes, int n_in,
                              void* d_out, int out_size) {
    const float* za     = (const float*)d_in[0];
    const float* zb     = (const float*)d_in[1];
    const int*   labels = (const int*)d_in[2];
    int N = in_sizes[2];   // labels element count

    k1_hist<<<HIST_BLOCKS, 256>>>(labels, N);
    k2_prefix<<<1, 32>>>();
    k1b_cvt<<<CVT_BLOCKS, 256>>>(za, zb, labels, N);
    k5_gram<<<dim3(N_TILES, C_CLASSES, 2), 256>>>();
    k5b_meanvar<<<32, 256>>>();
    k5c_cov<<<dim3(N_TILES, C_CLASSES, 2), 256>>>();
    k6_final<<<1, 256>>>((float*)d_out, N);
}

// round 9
// speedup vs baseline: 1.7668x; 1.1316x over previous
#include <cuda_runtime.h>
#include <cuda_bf16.h>
#include <math.h>

// Problem constants (fixed by the benchmark's setup_inputs)
#define C_CLASSES 16
#define D_DIM     256
#define N_MAX     32768
#define N_TILES   10          // upper-triangle 64x64 tiles of a 256x256 gram
#define LAM   25.0f
#define MU    25.0f
#define NU     1.0f
#define ALPHA 50.0f
#define EPS_V  1e-4f

#define NCHUNK (N_MAX / 32)   // 1024 chunks of 32 rows
#define CVT_BLOCKS NCHUNK

// ---------------- scratch (device globals; no allocation allowed) ----------
__device__ int   g_chunk_hist[NCHUNK][C_CLASSES];
__device__ int   g_chunk_base[NCHUNK][C_CLASSES];
__device__ int   g_rank[N_MAX];                     // (label<<16) | rank
__device__ int   g_counts[C_CLASSES];
__device__ int   g_offsets[C_CLASSES];
__device__ float g_mean[2 * C_CLASSES * D_DIM];     // [view][class][d]
__device__ float g_var [2 * C_CLASSES * D_DIM];
__device__ float g_colsum[2][C_CLASSES][D_DIM];     // written by diag blocks
__device__ float g_gram[2][C_CLASSES][N_TILES][64 * 64];  // raw gram tiles
__device__ float g_inv_partial[CVT_BLOCKS];
__device__ float g_cov_partial[2 * C_CLASSES * N_TILES];
__device__ __nv_bfloat16 g_xa[N_MAX * D_DIM];       // class-sorted bf16 rows
__device__ __nv_bfloat16 g_xb[N_MAX * D_DIM];

// ---------------- helpers ---------------------------------------------------
__device__ __forceinline__ float block_reduce_256(float v, float* red) {
    int tid = threadIdx.x;
    red[tid] = v;
    __syncthreads();
    #pragma unroll
    for (int s = 128; s > 0; s >>= 1) {
        if (tid < s) red[tid] += red[tid + s];
        __syncthreads();
    }
    float r = red[0];
    __syncthreads();
    return r;
}

__device__ __forceinline__ void ldsm4t(unsigned& r0, unsigned& r1,
                                       unsigned& r2, unsigned& r3,
                                       unsigned addr) {
    asm volatile("ldmatrix.sync.aligned.m8n8.x4.trans.shared.b16 {%0,%1,%2,%3}, [%4];\n"
                 : "=r"(r0), "=r"(r1), "=r"(r2), "=r"(r3) : "r"(addr));
}

__device__ __forceinline__ void mma16816(float* c, unsigned a0, unsigned a1,
                                         unsigned a2, unsigned a3,
                                         unsigned b0, unsigned b1) {
    asm volatile("mma.sync.aligned.m16n8k16.row.col.f32.bf16.bf16.f32 "
                 "{%0,%1,%2,%3}, {%4,%5,%6,%7}, {%8,%9}, {%0,%1,%2,%3};\n"
                 : "+f"(c[0]), "+f"(c[1]), "+f"(c[2]), "+f"(c[3])
                 : "r"(a0), "r"(a1), "r"(a2), "r"(a3), "r"(b0), "r"(b1));
}

__device__ __forceinline__ void cpa16(void* dst, const void* src, bool pred) {
    unsigned d = (unsigned)__cvta_generic_to_shared(dst);
    int sz = pred ? 16 : 0;
    asm volatile("cp.async.cg.shared.global [%0], [%1], 16, %2;\n"
                 :: "r"(d), "l"(src), "r"(sz));
}
__device__ __forceinline__ void cpa_commit() {
    asm volatile("cp.async.commit_group;\n");
}
__device__ __forceinline__ void cpa_wait2() {
    asm volatile("cp.async.wait_group 2;\n");
}

__device__ __forceinline__ unsigned pack_bf162(float x, float y) {
    __nv_bfloat162 h = __floats2bfloat162_rn(x, y);
    return *reinterpret_cast<unsigned*>(&h);
}

// ---------------- K1: per-chunk histogram + per-row rank (ballot) -----------
// chunk = 32 consecutive rows = one warp. grid 128 x 256 covers all 1024 chunks.
__global__ void k1_hist(const int* __restrict__ labels, int N) {
    int lane  = threadIdx.x & 31;
    int chunk = blockIdx.x * 8 + (threadIdx.x >> 5);
    int row   = chunk * 32 + lane;
    int lab   = (row < N) ? labels[row] : C_CLASSES;   // sentinel for OOB
    if (lane < C_CLASSES) g_chunk_hist[chunk][lane] = 0;
    __syncwarp();
    unsigned mask = __match_any_sync(0xffffffffu, lab);
    int rank = __popc(mask & ((1u << lane) - 1u));
    int leader = __ffs(mask) - 1;
    if (lab < C_CLASSES) {
        if (lane == leader) g_chunk_hist[chunk][lab] = __popc(mask);
        g_rank[row] = (lab << 16) | rank;
    }
}

// ---------------- K2: two-level scan -> per-chunk class bases ---------------
__global__ void __launch_bounds__(512) k2_scan() {
    __shared__ int ssum[32][C_CLASSES];
    __shared__ int sbase[32][C_CLASSES];
    __shared__ int soff[C_CLASSES];
    int t = threadIdx.x;          // 0..511
    int sb = t >> 4, c = t & 15;  // superblock 0..31, class 0..15
    int s = 0;
    #pragma unroll 4
    for (int k = 0; k < 32; k++) s += g_chunk_hist[sb * 32 + k][c];
    ssum[sb][c] = s;
    __syncthreads();
    if (t < C_CLASSES) {
        int run = 0;
        for (int b = 0; b < 32; b++) { sbase[b][t] = run; run += ssum[b][t]; }
        g_counts[t] = run;
    }
    __syncthreads();
    if (t == 0) {
        int o = 0;
        for (int cc = 0; cc < C_CLASSES; cc++) {
            soff[cc] = o;
            g_offsets[cc] = o;
            o += g_counts[cc];
        }
    }
    __syncthreads();
    int run = soff[c] + sbase[sb][c];
    for (int k = 0; k < 32; k++) {
        int ch = sb * 32 + k;
        g_chunk_base[ch][c] = run;
        run += g_chunk_hist[ch][c];
    }
}

// ---------------- K1b: convert + deterministic sorted scatter + invariance --
// Block = one 32-row chunk; warp w copies rows w*4..w*4+3 (lane covers 8 dims
// per view). No atomics: pos = chunk_base[chunk][lab] + rank.
__global__ void __launch_bounds__(256) k1b_cvt(const float* __restrict__ za,
                                               const float* __restrict__ zb,
                                               int N) {
    __shared__ float red[256];
    int tid  = threadIdx.x;
    int lane = tid & 31;
    int w    = tid >> 5;
    int chunk = blockIdx.x;

    float s = 0.f;
    #pragma unroll
    for (int i = 0; i < 4; i++) {
        int row = chunk * 32 + w * 4 + i;
        if (row < N) {
            int lr  = g_rank[row];                       // warp-uniform load
            int pos = g_chunk_base[chunk][lr >> 16] + (lr & 0xffff);

            const float4* pa = (const float4*)(za + (long)row * D_DIM);
            const float4* pb = (const float4*)(zb + (long)row * D_DIM);
            float4 a0 = __ldcs(pa + lane * 2), a1 = __ldcs(pa + lane * 2 + 1);
            float4 b0 = __ldcs(pb + lane * 2), b1 = __ldcs(pb + lane * 2 + 1);

            float dx = a0.x - b0.x, dy = a0.y - b0.y, dz = a0.z - b0.z, dw = a0.w - b0.w;
            s += dx * dx + dy * dy + dz * dz + dw * dw;
            dx = a1.x - b1.x; dy = a1.y - b1.y; dz = a1.z - b1.z; dw = a1.w - b1.w;
            s += dx * dx + dy * dy + dz * dz + dw * dw;

            uint4 wa, wb;
            wa.x = pack_bf162(a0.x, a0.y); wa.y = pack_bf162(a0.z, a0.w);
            wa.z = pack_bf162(a1.x, a1.y); wa.w = pack_bf162(a1.z, a1.w);
            wb.x = pack_bf162(b0.x, b0.y); wb.y = pack_bf162(b0.z, b0.w);
            wb.z = pack_bf162(b1.x, b1.y); wb.w = pack_bf162(b1.z, b1.w);
            ((uint4*)(g_xa + (long)pos * D_DIM))[lane] = wa;
            ((uint4*)(g_xb + (long)pos * D_DIM))[lane] = wb;
        }
    }
    s = block_reduce_256(s, red);
    if (tid == 0) g_inv_partial[chunk] = s;
}

// ---------------- K5: bf16 tensor-core RAW gram + colsum (smem FADD) --------
__constant__ int c_ti[N_TILES] = {0,0,0,0,1,1,1,2,2,3};
__constant__ int c_tj[N_TILES] = {0,1,2,3,1,2,3,2,3,3};

#define KCHUNK 32
#define NSTAGE 3

__global__ void __launch_bounds__(256, 4) k5_gram() {
    int t = blockIdx.x;
    int c = blockIdx.y;
    int v = blockIdx.z;
    const __nv_bfloat16* __restrict__ x = v ? g_xb : g_xa;
    int ti = c_ti[t], tj = c_tj[t];
    bool diag = (ti == tj);

    __shared__ __nv_bfloat16 As[NSTAGE][KCHUNK][72];
    __shared__ __nv_bfloat16 Bs[NSTAGE][KCHUNK][72];
    __shared__ float red[256];

    int n    = g_counts[c];
    int base = g_offsets[c];
    int tid  = threadIdx.x;
    int lane = tid & 31;
    int warp = tid >> 5;

    int m0 = (warp >> 1) * 16;     // warp's m-block within 64
    int nh = (warp & 1) * 32;      // warp's n-half within 64

    unsigned aBase = (unsigned)__cvta_generic_to_shared(&As[0][0][0]);
    unsigned bBase = diag ? aBase
                          : (unsigned)__cvta_generic_to_shared(&Bs[0][0][0]);
    const unsigned STAGE = KCHUNK * 72 * 2;   // bytes per stage
    int a_row = (lane & 7) + ((lane >> 4) & 1) * 8;          // k within 16
    int a_col = m0 + ((lane >> 3) & 1) * 8;                  // m
    unsigned aAddr = aBase + (unsigned)(a_row * 72 + a_col) * 2u;
    int b_row = (lane & 7) + ((lane >> 3) & 1) * 8;          // k within 16
    int b_col = nh + ((lane >> 4) & 1) * 8;                  // n
    unsigned bAddr0 = bBase + (unsigned)(b_row * 72 + b_col) * 2u;
    unsigned bAddr1 = bAddr0 + 16u * 2u;                     // n-tiles +16

    // staging: one 16B segment per thread (32 rows x 8 segs = 256 tasks)
    int kr  = tid >> 3;    // 0..31
    int seg = tid & 7;     // 0..7

    // colsum assignment (diag blocks): col = tid&63, rows (tid>>6)*8..+7
    int cs_col = tid & 63;
    int cs_r0  = (tid >> 6) * 8;
    float cs = 0.f;

    int nchunks = (n + KCHUNK - 1) / KCHUNK;

    #define ISSUE(ci, st) do {                                             \
        int kk = (ci) * KCHUNK + kr;                                       \
        bool pv = kk < n;                                                  \
        const __nv_bfloat16* rp = x + (long)(base + kk) * D_DIM;           \
        cpa16(&As[st][kr][seg * 8], rp + ti * 64 + seg * 8, pv);           \
        if (!diag)                                                         \
            cpa16(&Bs[st][kr][seg * 8], rp + tj * 64 + seg * 8, pv);       \
    } while (0)

    float acc[4][4] = {};    // [n-tile 0..3][c0..c3]

    ISSUE(0, 0);
    cpa_commit();
    if (nchunks > 1) ISSUE(1, 1);
    cpa_commit();
    for (int ci = 0; ci < nchunks; ci++) {
        if (ci + 2 < nchunks) {
            int st = (ci + 2) % NSTAGE;
            ISSUE(ci + 2, st);
        }
        cpa_commit();
        cpa_wait2();
        __syncthreads();
        int st = ci % NSTAGE;
        unsigned sOff = (unsigned)st * STAGE;
        #pragma unroll
        for (int ks = 0; ks < KCHUNK; ks += 16) {
            unsigned off = sOff + (unsigned)(ks * 72) * 2u;
            unsigned a0, a1, a2, a3;
            unsigned p0, p1, p2, p3;
            unsigned q0, q1, q2, q3;
            ldsm4t(a0, a1, a2, a3, aAddr + off);
            ldsm4t(p0, p1, p2, p3, bAddr0 + off);
            ldsm4t(q0, q1, q2, q3, bAddr1 + off);
            mma16816(acc[0], a0, a1, a2, a3, p0, p1);
            mma16816(acc[1], a0, a1, a2, a3, p2, p3);
            mma16816(acc[2], a0, a1, a2, a3, q0, q1);
            mma16816(acc[3], a0, a1, a2, a3, q2, q3);
        }
        if (diag) {
            #pragma unroll
            for (int u = 0; u < 8; u++)
                cs += __bfloat162float(As[st][cs_r0 + u][cs_col]);
        }
        __syncthreads();
    }

    // ---- write raw gram tile ----
    float* G = g_gram[v][c][t];
    int g  = lane >> 2;       // 0..7
    int tg = lane & 3;        // 0..3
    int r0 = m0 + g, r1 = m0 + g + 8;
    #pragma unroll
    for (int nt = 0; nt < 4; nt++) {
        int col = nh + nt * 8 + 2 * tg;
        *(float2*)&G[r0 * 64 + col] = make_float2(acc[nt][0], acc[nt][1]);
        *(float2*)&G[r1 * 64 + col] = make_float2(acc[nt][2], acc[nt][3]);
    }

    // ---- diag blocks: reduce + write colsums ----
    if (diag) {
        red[tid] = cs;
        __syncthreads();
        if (tid < 64)
            g_colsum[v][c][ti * 64 + tid] =
                red[tid] + red[tid + 64] + red[tid + 128] + red[tid + 192];
    }
}

// ---------------- K5b: mean/var from colsum + gram diagonal -----------------
__constant__ int c_diagt[4] = {0, 4, 7, 9};

__global__ void k5b_meanvar() {
    int o = blockIdx.x * 256 + threadIdx.x;   // grid 32 -> 8192 entries
    int d = o & (D_DIM - 1);
    int c = (o >> 8) & (C_CLASSES - 1);
    int v = o >> 12;
    float fn = (float)g_counts[c];
    float m = g_colsum[v][c][d] / fn;
    g_mean[o] = m;
    int s = d >> 6, dd = d & 63;
    float Gdd = g_gram[v][c][c_diagt[s]][dd * 64 + dd];
    g_var[o] = (Gdd - fn * m * m) / (fn - 1.f);
}

// ---------------- K5c: covariance partials from raw gram + means ------------
__global__ void __launch_bounds__(256) k5c_cov() {
    int t = blockIdx.x;
    int c = blockIdx.y;
    int v = blockIdx.z;
    int ti = c_ti[t], tj = c_tj[t];
    bool diag = (ti == tj);

    __shared__ float mi[64], mj[64];
    __shared__ float red[256];
    int tid = threadIdx.x;
    int vc = v * C_CLASSES + c;
    const float* mrow = &g_mean[vc * D_DIM];
    if (tid < 64)        mi[tid]      = mrow[ti * 64 + tid];
    else if (tid < 128)  mj[tid - 64] = mrow[tj * 64 + tid - 64];
    __syncthreads();

    const float* __restrict__ G = g_gram[v][c][t];
    float fn = (float)g_counts[c];
    float inv_nm1 = 1.f / (fn - 1.f);
    float wgt_tile = diag ? 1.f : 2.f;

    float sum = 0.f;
    #pragma unroll
    for (int k = 0; k < 16; k++) {
        int idx = tid + k * 256;
        int r = idx >> 6, col = idx & 63;
        float cv = (G[idx] - fn * mi[r] * mj[col]) * inv_nm1;
        float w = (diag && r == col) ? 0.f : wgt_tile;
        sum += w * cv * cv;
    }
    sum = block_reduce_256(sum, red);
    if (tid == 0) g_cov_partial[vc * N_TILES + t] = sum;
}

// ---------------- K6: finalize all terms ------------------------------------
__global__ void k6_final(float* __restrict__ out, int N) {
    __shared__ float m[C_CLASSES * D_DIM];
    __shared__ float red[256];
    int tid = threadIdx.x;

    for (int e = tid; e < C_CLASSES * D_DIM; e += 256)
        m[e] = 0.5f * (g_mean[e] + g_mean[C_CLASSES * D_DIM + e]);

    // invariance partials
    float inv_sum = 0.f;
    for (int e = tid; e < CVT_BLOCKS; e += 256) inv_sum += g_inv_partial[e];
    inv_sum = block_reduce_256(inv_sum, red);

    // variance
    float vsum = 0.f;
    for (int e = tid; e < 2 * C_CLASSES * D_DIM; e += 256) {
        float vv = g_var[e];
        vsum += fmaxf(0.f, 1.f - sqrtf(vv + EPS_V));
    }
    vsum = block_reduce_256(vsum, red);

    // covariance
    float csum = 0.f;
    for (int e = tid; e < 2 * C_CLASSES * N_TILES; e += 256)
        csum += g_cov_partial[e];
    csum = block_reduce_256(csum, red);

    // class-discriminative margin (120 pairs)
    float psum = 0.f;
    const int npairs = C_CLASSES * (C_CLASSES - 1) / 2;
    if (tid < npairs) {
        int i = 0, rem = tid;
        while (rem >= C_CLASSES - 1 - i) { rem -= C_CLASSES - 1 - i; i++; }
        int j = i + 1 + rem;
        float d2 = 0.f;
        for (int d = 0; d < D_DIM; d++) {
            float df = m[i * D_DIM + d] - m[j * D_DIM + d];
            d2 += df * df;
        }
        float dist = sqrtf(d2);
        float rr = fmaxf(0.f, ALPHA - dist);
        psum = rr * rr;
    }
    psum = block_reduce_256(psum, red);

    if (tid == 0) {
        float inv_loss   = inv_sum / ((float)N * (float)D_DIM);
        float var_loss   = vsum * 0.5f / ((float)C_CLASSES * (float)D_DIM);
        float cov_loss   = csum * 0.5f / ((float)C_CLASSES * (float)D_DIM);
        float class_loss = psum / (float)npairs;
        out[0] = LAM * inv_loss + MU * var_loss + NU * cov_loss + ALPHA * class_loss;
    }
}

// ---------------- launch -----------------------------------------------------
extern "C" void kernel_launch(void* const* d_in, const int* in_sizes, int n_in,
                              void* d_out, int out_size) {
    const float* za     = (const float*)d_in[0];
    const float* zb     = (const float*)d_in[1];
    const int*   labels = (const int*)d_in[2];
    int N = in_sizes[2];   // labels element count

    // Allow full smem carveout so 4 k5 blocks fit per SM (idempotent).
    cudaFuncSetAttribute((const void*)k5_gram,
                         cudaFuncAttributePreferredSharedMemoryCarveout, 100);

    k1_hist<<<NCHUNK / 8, 256>>>(labels, N);
    k2_scan<<<1, 512>>>();
    k1b_cvt<<<NCHUNK, 256>>>(za, zb, N);
    k5_gram<<<dim3(N_TILES, C_CLASSES, 2), 256>>>();
    k5b_meanvar<<<32, 256>>>();
    k5c_cov<<<dim3(N_TILES, C_CLASSES, 2), 256>>>();
    k6_final<<<1, 256>>>((float*)d_out, N);
}

// round 10
// speedup vs baseline: 1.8037x; 1.0209x over previous
#include <cuda_runtime.h>
#include <cuda_bf16.h>
#include <math.h>

// Problem constants (fixed by the benchmark's setup_inputs)
#define C_CLASSES 16
#define D_DIM     256
#define N_MAX     32768
#define N_TILES   10          // upper-triangle 64x64 tiles of a 256x256 gram
#define LAM   25.0f
#define MU    25.0f
#define NU     1.0f
#define ALPHA 50.0f
#define EPS_V  1e-4f

#define NCHUNK (N_MAX / 32)   // 1024 chunks of 32 rows
#define CVT_BLOCKS NCHUNK
#define KSPLIT 2              // K-dimension split of the gram reduction

// ---------------- scratch (device globals; no allocation allowed) ----------
__device__ int   g_chunk_hist[NCHUNK][C_CLASSES];
__device__ int   g_chunk_base[NCHUNK][C_CLASSES];
__device__ int   g_rank[N_MAX];                     // (label<<16) | rank
__device__ int   g_counts[C_CLASSES];
__device__ int   g_offsets[C_CLASSES];
__device__ float g_mean[2 * C_CLASSES * D_DIM];     // [view][class][d]
__device__ float g_var [2 * C_CLASSES * D_DIM];
__device__ float g_colsum[KSPLIT][2][C_CLASSES][D_DIM];
__device__ float g_gram[KSPLIT][2][C_CLASSES][N_TILES][64 * 64];
__device__ float g_inv_partial[CVT_BLOCKS];
__device__ float g_cov_partial[2 * C_CLASSES * N_TILES];
__device__ __nv_bfloat16 g_xa[N_MAX * D_DIM];       // class-sorted bf16 rows
__device__ __nv_bfloat16 g_xb[N_MAX * D_DIM];

// ---------------- helpers ---------------------------------------------------
__device__ __forceinline__ float block_reduce_256(float v, float* red) {
    int tid = threadIdx.x;
    red[tid] = v;
    __syncthreads();
    #pragma unroll
    for (int s = 128; s > 0; s >>= 1) {
        if (tid < s) red[tid] += red[tid + s];
        __syncthreads();
    }
    float r = red[0];
    __syncthreads();
    return r;
}

__device__ __forceinline__ void ldsm4t(unsigned& r0, unsigned& r1,
                                       unsigned& r2, unsigned& r3,
                                       unsigned addr) {
    asm volatile("ldmatrix.sync.aligned.m8n8.x4.trans.shared.b16 {%0,%1,%2,%3}, [%4];\n"
                 : "=r"(r0), "=r"(r1), "=r"(r2), "=r"(r3) : "r"(addr));
}

__device__ __forceinline__ void mma16816(float* c, unsigned a0, unsigned a1,
                                         unsigned a2, unsigned a3,
                                         unsigned b0, unsigned b1) {
    asm volatile("mma.sync.aligned.m16n8k16.row.col.f32.bf16.bf16.f32 "
                 "{%0,%1,%2,%3}, {%4,%5,%6,%7}, {%8,%9}, {%0,%1,%2,%3};\n"
                 : "+f"(c[0]), "+f"(c[1]), "+f"(c[2]), "+f"(c[3])
                 : "r"(a0), "r"(a1), "r"(a2), "r"(a3), "r"(b0), "r"(b1));
}

__device__ __forceinline__ void cpa16(void* dst, const void* src, bool pred) {
    unsigned d = (unsigned)__cvta_generic_to_shared(dst);
    int sz = pred ? 16 : 0;
    asm volatile("cp.async.cg.shared.global [%0], [%1], 16, %2;\n"
                 :: "r"(d), "l"(src), "r"(sz));
}
__device__ __forceinline__ void cpa_commit() {
    asm volatile("cp.async.commit_group;\n");
}
__device__ __forceinline__ void cpa_wait2() {
    asm volatile("cp.async.wait_group 2;\n");
}

__device__ __forceinline__ unsigned pack_bf162(float x, float y) {
    __nv_bfloat162 h = __floats2bfloat162_rn(x, y);
    return *reinterpret_cast<unsigned*>(&h);
}

// ---------------- K1: per-chunk histogram + per-row rank (ballot) -----------
__global__ void k1_hist(const int* __restrict__ labels, int N) {
    int lane  = threadIdx.x & 31;
    int chunk = blockIdx.x * 8 + (threadIdx.x >> 5);
    int row   = chunk * 32 + lane;
    int lab   = (row < N) ? labels[row] : C_CLASSES;   // sentinel for OOB
    if (lane < C_CLASSES) g_chunk_hist[chunk][lane] = 0;
    __syncwarp();
    unsigned mask = __match_any_sync(0xffffffffu, lab);
    int rank = __popc(mask & ((1u << lane) - 1u));
    int leader = __ffs(mask) - 1;
    if (lab < C_CLASSES) {
        if (lane == leader) g_chunk_hist[chunk][lab] = __popc(mask);
        g_rank[row] = (lab << 16) | rank;
    }
}

// ---------------- K2: two-level scan -> per-chunk class bases ---------------
__global__ void __launch_bounds__(512) k2_scan() {
    __shared__ int ssum[32][C_CLASSES];
    __shared__ int sbase[32][C_CLASSES];
    __shared__ int soff[C_CLASSES];
    int t = threadIdx.x;          // 0..511
    int sb = t >> 4, c = t & 15;  // superblock 0..31, class 0..15
    int s = 0;
    #pragma unroll 4
    for (int k = 0; k < 32; k++) s += g_chunk_hist[sb * 32 + k][c];
    ssum[sb][c] = s;
    __syncthreads();
    if (t < C_CLASSES) {
        int run = 0;
        for (int b = 0; b < 32; b++) { sbase[b][t] = run; run += ssum[b][t]; }
        g_counts[t] = run;
    }
    __syncthreads();
    if (t == 0) {
        int o = 0;
        for (int cc = 0; cc < C_CLASSES; cc++) {
            soff[cc] = o;
            g_offsets[cc] = o;
            o += g_counts[cc];
        }
    }
    __syncthreads();
    int run = soff[c] + sbase[sb][c];
    for (int k = 0; k < 32; k++) {
        int ch = sb * 32 + k;
        g_chunk_base[ch][c] = run;
        run += g_chunk_hist[ch][c];
    }
}

// ---------------- K1b: convert + deterministic sorted scatter + invariance --
__global__ void __launch_bounds__(256) k1b_cvt(const float* __restrict__ za,
                                               const float* __restrict__ zb,
                                               int N) {
    __shared__ float red[256];
    int tid  = threadIdx.x;
    int lane = tid & 31;
    int w    = tid >> 5;
    int chunk = blockIdx.x;

    float s = 0.f;
    #pragma unroll
    for (int i = 0; i < 4; i++) {
        int row = chunk * 32 + w * 4 + i;
        if (row < N) {
            int lr  = g_rank[row];                       // warp-uniform load
            int pos = g_chunk_base[chunk][lr >> 16] + (lr & 0xffff);

            const float4* pa = (const float4*)(za + (long)row * D_DIM);
            const float4* pb = (const float4*)(zb + (long)row * D_DIM);
            float4 a0 = __ldcs(pa + lane * 2), a1 = __ldcs(pa + lane * 2 + 1);
            float4 b0 = __ldcs(pb + lane * 2), b1 = __ldcs(pb + lane * 2 + 1);

            float dx = a0.x - b0.x, dy = a0.y - b0.y, dz = a0.z - b0.z, dw = a0.w - b0.w;
            s += dx * dx + dy * dy + dz * dz + dw * dw;
            dx = a1.x - b1.x; dy = a1.y - b1.y; dz = a1.z - b1.z; dw = a1.w - b1.w;
            s += dx * dx + dy * dy + dz * dz + dw * dw;

            uint4 wa, wb;
            wa.x = pack_bf162(a0.x, a0.y); wa.y = pack_bf162(a0.z, a0.w);
            wa.z = pack_bf162(a1.x, a1.y); wa.w = pack_bf162(a1.z, a1.w);
            wb.x = pack_bf162(b0.x, b0.y); wb.y = pack_bf162(b0.z, b0.w);
            wb.z = pack_bf162(b1.x, b1.y); wb.w = pack_bf162(b1.z, b1.w);
            ((uint4*)(g_xa + (long)pos * D_DIM))[lane] = wa;
            ((uint4*)(g_xb + (long)pos * D_DIM))[lane] = wb;
        }
    }
    s = block_reduce_256(s, red);
    if (tid == 0) g_inv_partial[chunk] = s;
}

// ---------------- K5: bf16 tensor-core partial gram (K-split) ---------------
// Block = (tile + slice*N_TILES, class, view). Each block reduces one of
// KSPLIT row-slices of its class; partial gram -> g_gram[slice].
__constant__ int c_ti[N_TILES] = {0,0,0,0,1,1,1,2,2,3};
__constant__ int c_tj[N_TILES] = {0,1,2,3,1,2,3,2,3,3};

#define KCHUNK 32
#define NSTAGE 3

__global__ void __launch_bounds__(256, 4) k5_gram() {
    int bx = blockIdx.x;
    int t = bx % N_TILES;
    int slice = bx / N_TILES;
    int c = blockIdx.y;
    int v = blockIdx.z;
    const __nv_bfloat16* __restrict__ x = v ? g_xb : g_xa;
    int ti = c_ti[t], tj = c_tj[t];
    bool diag = (ti == tj);

    __shared__ __nv_bfloat16 As[NSTAGE][KCHUNK][72];
    __shared__ __nv_bfloat16 Bs[NSTAGE][KCHUNK][72];
    __shared__ float red[256];

    int n = g_counts[c];
    int lo  = (int)(((long)n * slice) / KSPLIT);
    int hi  = (int)(((long)n * (slice + 1)) / KSPLIT);
    int cnt = hi - lo;
    int base = g_offsets[c] + lo;

    int tid  = threadIdx.x;
    int lane = tid & 31;
    int warp = tid >> 5;

    int m0 = (warp >> 1) * 16;     // warp's m-block within 64
    int nh = (warp & 1) * 32;      // warp's n-half within 64

    unsigned aBase = (unsigned)__cvta_generic_to_shared(&As[0][0][0]);
    unsigned bBase = diag ? aBase
                          : (unsigned)__cvta_generic_to_shared(&Bs[0][0][0]);
    const unsigned STAGE = KCHUNK * 72 * 2;   // bytes per stage
    int a_row = (lane & 7) + ((lane >> 4) & 1) * 8;          // k within 16
    int a_col = m0 + ((lane >> 3) & 1) * 8;                  // m
    unsigned aAddr = aBase + (unsigned)(a_row * 72 + a_col) * 2u;
    int b_row = (lane & 7) + ((lane >> 3) & 1) * 8;          // k within 16
    int b_col = nh + ((lane >> 4) & 1) * 8;                  // n
    unsigned bAddr0 = bBase + (unsigned)(b_row * 72 + b_col) * 2u;
    unsigned bAddr1 = bAddr0 + 16u * 2u;                     // n-tiles +16

    // staging: one 16B segment per thread (32 rows x 8 segs = 256 tasks)
    int kr  = tid >> 3;    // 0..31
    int seg = tid & 7;     // 0..7

    // colsum assignment (diag blocks): col = tid&63, rows (tid>>6)*8..+7
    int cs_col = tid & 63;
    int cs_r0  = (tid >> 6) * 8;
    float cs = 0.f;

    int nchunks = (cnt + KCHUNK - 1) / KCHUNK;

    #define ISSUE(ci, st) do {                                             \
        int kk = (ci) * KCHUNK + kr;                                       \
        bool pv = kk < cnt;                                                \
        const __nv_bfloat16* rp = x + (long)(base + kk) * D_DIM;           \
        cpa16(&As[st][kr][seg * 8], rp + ti * 64 + seg * 8, pv);           \
        if (!diag)                                                         \
            cpa16(&Bs[st][kr][seg * 8], rp + tj * 64 + seg * 8, pv);       \
    } while (0)

    float acc[4][4] = {};    // [n-tile 0..3][c0..c3]

    ISSUE(0, 0);
    cpa_commit();
    if (nchunks > 1) ISSUE(1, 1);
    cpa_commit();
    for (int ci = 0; ci < nchunks; ci++) {
        if (ci + 2 < nchunks) {
            int st = (ci + 2) % NSTAGE;
            ISSUE(ci + 2, st);
        }
        cpa_commit();
        cpa_wait2();
        __syncthreads();
        int st = ci % NSTAGE;
        unsigned sOff = (unsigned)st * STAGE;
        #pragma unroll
        for (int ks = 0; ks < KCHUNK; ks += 16) {
            unsigned off = sOff + (unsigned)(ks * 72) * 2u;
            unsigned a0, a1, a2, a3;
            unsigned p0, p1, p2, p3;
            unsigned q0, q1, q2, q3;
            ldsm4t(a0, a1, a2, a3, aAddr + off);
            ldsm4t(p0, p1, p2, p3, bAddr0 + off);
            ldsm4t(q0, q1, q2, q3, bAddr1 + off);
            mma16816(acc[0], a0, a1, a2, a3, p0, p1);
            mma16816(acc[1], a0, a1, a2, a3, p2, p3);
            mma16816(acc[2], a0, a1, a2, a3, q0, q1);
            mma16816(acc[3], a0, a1, a2, a3, q2, q3);
        }
        if (diag) {
            #pragma unroll
            for (int u = 0; u < 8; u++)
                cs += __bfloat162float(As[st][cs_r0 + u][cs_col]);
        }
        __syncthreads();
    }

    // ---- write partial gram tile ----
    float* G = g_gram[slice][v][c][t];
    int g  = lane >> 2;       // 0..7
    int tg = lane & 3;        // 0..3
    int r0 = m0 + g, r1 = m0 + g + 8;
    #pragma unroll
    for (int nt = 0; nt < 4; nt++) {
        int col = nh + nt * 8 + 2 * tg;
        *(float2*)&G[r0 * 64 + col] = make_float2(acc[nt][0], acc[nt][1]);
        *(float2*)&G[r1 * 64 + col] = make_float2(acc[nt][2], acc[nt][3]);
    }

    // ---- diag blocks: reduce + write partial colsums ----
    if (diag) {
        red[tid] = cs;
        __syncthreads();
        if (tid < 64)
            g_colsum[slice][v][c][ti * 64 + tid] =
                red[tid] + red[tid + 64] + red[tid + 128] + red[tid + 192];
    }
}

// ---------------- K5b: mean/var from colsum + gram diagonal -----------------
__constant__ int c_diagt[4] = {0, 4, 7, 9};

__global__ void k5b_meanvar() {
    int o = blockIdx.x * 256 + threadIdx.x;   // grid 32 -> 8192 entries
    int d = o & (D_DIM - 1);
    int c = (o >> 8) & (C_CLASSES - 1);
    int v = o >> 12;
    float fn = (float)g_counts[c];
    float colsum = 0.f, Gdd = 0.f;
    int s = d >> 6, dd = d & 63;
    #pragma unroll
    for (int sl = 0; sl < KSPLIT; sl++) {
        colsum += g_colsum[sl][v][c][d];
        Gdd    += g_gram[sl][v][c][c_diagt[s]][dd * 64 + dd];
    }
    float m = colsum / fn;
    g_mean[o] = m;
    g_var[o] = (Gdd - fn * m * m) / (fn - 1.f);
}

// ---------------- K5c: covariance partials from summed gram + means ---------
__global__ void __launch_bounds__(256) k5c_cov() {
    int t = blockIdx.x;
    int c = blockIdx.y;
    int v = blockIdx.z;
    int ti = c_ti[t], tj = c_tj[t];
    bool diag = (ti == tj);

    __shared__ float mi[64], mj[64];
    __shared__ float red[256];
    int tid = threadIdx.x;
    int vc = v * C_CLASSES + c;
    const float* mrow = &g_mean[vc * D_DIM];
    if (tid < 64)        mi[tid]      = mrow[ti * 64 + tid];
    else if (tid < 128)  mj[tid - 64] = mrow[tj * 64 + tid - 64];
    __syncthreads();

    const float* __restrict__ G0 = g_gram[0][v][c][t];
    const float* __restrict__ G1 = g_gram[1][v][c][t];
    float fn = (float)g_counts[c];
    float inv_nm1 = 1.f / (fn - 1.f);
    float wgt_tile = diag ? 1.f : 2.f;

    float sum = 0.f;
    #pragma unroll
    for (int k = 0; k < 16; k++) {
        int idx = tid + k * 256;
        int r = idx >> 6, col = idx & 63;
        float cv = (G0[idx] + G1[idx] - fn * mi[r] * mj[col]) * inv_nm1;
        float w = (diag && r == col) ? 0.f : wgt_tile;
        sum += w * cv * cv;
    }
    sum = block_reduce_256(sum, red);
    if (tid == 0) g_cov_partial[vc * N_TILES + t] = sum;
}

// ---------------- K6: finalize all terms ------------------------------------
__global__ void k6_final(float* __restrict__ out, int N) {
    __shared__ float m[C_CLASSES * D_DIM];
    __shared__ float red[256];
    int tid = threadIdx.x;

    for (int e = tid; e < C_CLASSES * D_DIM; e += 256)
        m[e] = 0.5f * (g_mean[e] + g_mean[C_CLASSES * D_DIM + e]);

    // invariance partials
    float inv_sum = 0.f;
    for (int e = tid; e < CVT_BLOCKS; e += 256) inv_sum += g_inv_partial[e];
    inv_sum = block_reduce_256(inv_sum, red);

    // variance
    float vsum = 0.f;
    for (int e = tid; e < 2 * C_CLASSES * D_DIM; e += 256) {
        float vv = g_var[e];
        vsum += fmaxf(0.f, 1.f - sqrtf(vv + EPS_V));
    }
    vsum = block_reduce_256(vsum, red);

    // covariance
    float csum = 0.f;
    for (int e = tid; e < 2 * C_CLASSES * N_TILES; e += 256)
        csum += g_cov_partial[e];
    csum = block_reduce_256(csum, red);

    // class-discriminative margin (120 pairs)
    float psum = 0.f;
    const int npairs = C_CLASSES * (C_CLASSES - 1) / 2;
    if (tid < npairs) {
        int i = 0, rem = tid;
        while (rem >= C_CLASSES - 1 - i) { rem -= C_CLASSES - 1 - i; i++; }
        int j = i + 1 + rem;
        float d2 = 0.f;
        for (int d = 0; d < D_DIM; d++) {
            float df = m[i * D_DIM + d] - m[j * D_DIM + d];
            d2 += df * df;
        }
        float dist = sqrtf(d2);
        float rr = fmaxf(0.f, ALPHA - dist);
        psum = rr * rr;
    }
    psum = block_reduce_256(psum, red);

    if (tid == 0) {
        float inv_loss   = inv_sum / ((float)N * (float)D_DIM);
        float var_loss   = vsum * 0.5f / ((float)C_CLASSES * (float)D_DIM);
        float cov_loss   = csum * 0.5f / ((float)C_CLASSES * (float)D_DIM);
        float class_loss = psum / (float)npairs;
        out[0] = LAM * inv_loss + MU * var_loss + NU * cov_loss + ALPHA * class_loss;
    }
}

// ---------------- launch -----------------------------------------------------
extern "C" void kernel_launch(void* const* d_in, const int* in_sizes, int n_in,
                              void* d_out, int out_size) {
    const float* za     = (const float*)d_in[0];
    const float* zb     = (const float*)d_in[1];
    const int*   labels = (const int*)d_in[2];
    int N = in_sizes[2];   // labels element count

    k1_hist<<<NCHUNK / 8, 256>>>(labels, N);
    k2_scan<<<1, 512>>>();
    k1b_cvt<<<NCHUNK, 256>>>(za, zb, N);
    k5_gram<<<dim3(N_TILES * KSPLIT, C_CLASSES, 2), 256>>>();
    k5b_meanvar<<<32, 256>>>();
    k5c_cov<<<dim3(N_TILES, C_CLASSES, 2), 256>>>();
    k6_final<<<1, 256>>>((float*)d_out, N);
}

// round 11
// speedup vs baseline: 1.8909x; 1.0483x over previous
#include <cuda_runtime.h>
#include <cuda_bf16.h>
#include <math.h>

// Problem constants (fixed by the benchmark's setup_inputs)
#define C_CLASSES 16
#define D_DIM     256
#define N_MAX     32768
#define N_TILES   10          // upper-triangle 64x64 tiles of a 256x256 gram
#define LAM   25.0f
#define MU    25.0f
#define NU     1.0f
#define ALPHA 50.0f
#define EPS_V  1e-4f

#define NCHUNK (N_MAX / 32)   // 1024 chunks of 32 rows
#define CVT_BLOCKS NCHUNK
#define KSPLIT 2              // K-dimension split of the gram reduction

// ---------------- scratch (device globals; no allocation allowed) ----------
__device__ int   g_chunk_hist[NCHUNK][C_CLASSES];
__device__ int   g_chunk_base[NCHUNK][C_CLASSES];
__device__ int   g_rank[N_MAX];                     // (label<<16) | rank
__device__ int   g_counts[C_CLASSES];
__device__ int   g_offsets[C_CLASSES];
__device__ float g_mean[2 * C_CLASSES * D_DIM];     // [view][class][d]
__device__ float g_var [2 * C_CLASSES * D_DIM];
__device__ float g_colsum[KSPLIT][2][C_CLASSES][D_DIM];
__device__ float g_gram[KSPLIT][2][C_CLASSES][N_TILES][64 * 64];
__device__ float g_inv_partial[CVT_BLOCKS];
__device__ float g_cov_partial[2 * C_CLASSES * N_TILES];
__device__ __nv_bfloat16 g_xa[N_MAX * D_DIM];       // class-sorted bf16 rows
__device__ __nv_bfloat16 g_xb[N_MAX * D_DIM];

// ---------------- helpers ---------------------------------------------------
__device__ __forceinline__ float block_reduce_256(float v, float* red) {
    int tid = threadIdx.x;
    red[tid] = v;
    __syncthreads();
    #pragma unroll
    for (int s = 128; s > 0; s >>= 1) {
        if (tid < s) red[tid] += red[tid + s];
        __syncthreads();
    }
    float r = red[0];
    __syncthreads();
    return r;
}

__device__ __forceinline__ void ldsm4t(unsigned& r0, unsigned& r1,
                                       unsigned& r2, unsigned& r3,
                                       unsigned addr) {
    asm volatile("ldmatrix.sync.aligned.m8n8.x4.trans.shared.b16 {%0,%1,%2,%3}, [%4];\n"
                 : "=r"(r0), "=r"(r1), "=r"(r2), "=r"(r3) : "r"(addr));
}

__device__ __forceinline__ void mma16816(float* c, unsigned a0, unsigned a1,
                                         unsigned a2, unsigned a3,
                                         unsigned b0, unsigned b1) {
    asm volatile("mma.sync.aligned.m16n8k16.row.col.f32.bf16.bf16.f32 "
                 "{%0,%1,%2,%3}, {%4,%5,%6,%7}, {%8,%9}, {%0,%1,%2,%3};\n"
                 : "+f"(c[0]), "+f"(c[1]), "+f"(c[2]), "+f"(c[3])
                 : "r"(a0), "r"(a1), "r"(a2), "r"(a3), "r"(b0), "r"(b1));
}

__device__ __forceinline__ void cpa16(void* dst, const void* src, bool pred) {
    unsigned d = (unsigned)__cvta_generic_to_shared(dst);
    int sz = pred ? 16 : 0;
    asm volatile("cp.async.cg.shared.global [%0], [%1], 16, %2;\n"
                 :: "r"(d), "l"(src), "r"(sz));
}
__device__ __forceinline__ void cpa_commit() {
    asm volatile("cp.async.commit_group;\n");
}
__device__ __forceinline__ void cpa_wait2() {
    asm volatile("cp.async.wait_group 2;\n");
}

__device__ __forceinline__ unsigned pack_bf162(float x, float y) {
    __nv_bfloat162 h = __floats2bfloat162_rn(x, y);
    return *reinterpret_cast<unsigned*>(&h);
}

// ---------------- K1: per-chunk histogram + per-row rank (ballot) -----------
__global__ void k1_hist(const int* __restrict__ labels, int N) {
    int lane  = threadIdx.x & 31;
    int chunk = blockIdx.x * 8 + (threadIdx.x >> 5);
    int row   = chunk * 32 + lane;
    int lab   = (row < N) ? labels[row] : C_CLASSES;   // sentinel for OOB
    if (lane < C_CLASSES) g_chunk_hist[chunk][lane] = 0;
    __syncwarp();
    unsigned mask = __match_any_sync(0xffffffffu, lab);
    int rank = __popc(mask & ((1u << lane) - 1u));
    int leader = __ffs(mask) - 1;
    if (lab < C_CLASSES) {
        if (lane == leader) g_chunk_hist[chunk][lab] = __popc(mask);
        g_rank[row] = (lab << 16) | rank;
    }
}

// ---------------- K2: two-level scan -> per-chunk class bases ---------------
__global__ void __launch_bounds__(512) k2_scan() {
    __shared__ int ssum[32][C_CLASSES];
    __shared__ int sbase[32][C_CLASSES];
    __shared__ int soff[C_CLASSES];
    int t = threadIdx.x;          // 0..511
    int sb = t >> 4, c = t & 15;  // superblock 0..31, class 0..15
    int s = 0;
    #pragma unroll 4
    for (int k = 0; k < 32; k++) s += g_chunk_hist[sb * 32 + k][c];
    ssum[sb][c] = s;
    __syncthreads();
    if (t < C_CLASSES) {
        int run = 0;
        for (int b = 0; b < 32; b++) { sbase[b][t] = run; run += ssum[b][t]; }
        g_counts[t] = run;
    }
    __syncthreads();
    if (t == 0) {
        int o = 0;
        for (int cc = 0; cc < C_CLASSES; cc++) {
            soff[cc] = o;
            g_offsets[cc] = o;
            o += g_counts[cc];
        }
    }
    __syncthreads();
    int run = soff[c] + sbase[sb][c];
    for (int k = 0; k < 32; k++) {
        int ch = sb * 32 + k;
        g_chunk_base[ch][c] = run;
        run += g_chunk_hist[ch][c];
    }
}

// ---------------- K1b: convert + deterministic sorted scatter + invariance --
// Warp per row-pair: loads for TWO rows are issued before converting either
// (MLP 8 float4/thread) to hide DRAM latency.
__global__ void __launch_bounds__(256) k1b_cvt(const float* __restrict__ za,
                                               const float* __restrict__ zb,
                                               int N) {
    __shared__ float red[256];
    int tid  = threadIdx.x;
    int lane = tid & 31;
    int w    = tid >> 5;
    int chunk = blockIdx.x;

    float s = 0.f;
    #pragma unroll
    for (int i = 0; i < 4; i += 2) {
        int rowA = chunk * 32 + w * 4 + i;
        int rowB = rowA + 1;
        bool vA = rowA < N, vB = rowB < N;

        const float4* paA = (const float4*)(za + (long)rowA * D_DIM);
        const float4* pbA = (const float4*)(zb + (long)rowA * D_DIM);
        const float4* paB = (const float4*)(za + (long)rowB * D_DIM);
        const float4* pbB = (const float4*)(zb + (long)rowB * D_DIM);

        float4 a0A, a1A, b0A, b1A, a0B, a1B, b0B, b1B;
        if (vA) {
            a0A = __ldcs(paA + lane * 2); a1A = __ldcs(paA + lane * 2 + 1);
            b0A = __ldcs(pbA + lane * 2); b1A = __ldcs(pbA + lane * 2 + 1);
        }
        if (vB) {
            a0B = __ldcs(paB + lane * 2); a1B = __ldcs(paB + lane * 2 + 1);
            b0B = __ldcs(pbB + lane * 2); b1B = __ldcs(pbB + lane * 2 + 1);
        }

        if (vA) {
            int lr  = g_rank[rowA];
            int pos = g_chunk_base[chunk][lr >> 16] + (lr & 0xffff);
            float dx = a0A.x - b0A.x, dy = a0A.y - b0A.y,
                  dz = a0A.z - b0A.z, dw = a0A.w - b0A.w;
            s += dx * dx + dy * dy + dz * dz + dw * dw;
            dx = a1A.x - b1A.x; dy = a1A.y - b1A.y;
            dz = a1A.z - b1A.z; dw = a1A.w - b1A.w;
            s += dx * dx + dy * dy + dz * dz + dw * dw;
            uint4 wa, wb;
            wa.x = pack_bf162(a0A.x, a0A.y); wa.y = pack_bf162(a0A.z, a0A.w);
            wa.z = pack_bf162(a1A.x, a1A.y); wa.w = pack_bf162(a1A.z, a1A.w);
            wb.x = pack_bf162(b0A.x, b0A.y); wb.y = pack_bf162(b0A.z, b0A.w);
            wb.z = pack_bf162(b1A.x, b1A.y); wb.w = pack_bf162(b1A.z, b1A.w);
            ((uint4*)(g_xa + (long)pos * D_DIM))[lane] = wa;
            ((uint4*)(g_xb + (long)pos * D_DIM))[lane] = wb;
        }
        if (vB) {
            int lr  = g_rank[rowB];
            int pos = g_chunk_base[chunk][lr >> 16] + (lr & 0xffff);
            float dx = a0B.x - b0B.x, dy = a0B.y - b0B.y,
                  dz = a0B.z - b0B.z, dw = a0B.w - b0B.w;
            s += dx * dx + dy * dy + dz * dz + dw * dw;
            dx = a1B.x - b1B.x; dy = a1B.y - b1B.y;
            dz = a1B.z - b1B.z; dw = a1B.w - b1B.w;
            s += dx * dx + dy * dy + dz * dz + dw * dw;
            uint4 wa, wb;
            wa.x = pack_bf162(a0B.x, a0B.y); wa.y = pack_bf162(a0B.z, a0B.w);
            wa.z = pack_bf162(a1B.x, a1B.y); wa.w = pack_bf162(a1B.z, a1B.w);
            wb.x = pack_bf162(b0B.x, b0B.y); wb.y = pack_bf162(b0B.z, b0B.w);
            wb.z = pack_bf162(b1B.x, b1B.y); wb.w = pack_bf162(b1B.z, b1B.w);
            ((uint4*)(g_xa + (long)pos * D_DIM))[lane] = wa;
            ((uint4*)(g_xb + (long)pos * D_DIM))[lane] = wb;
        }
    }
    s = block_reduce_256(s, red);
    if (tid == 0) g_inv_partial[chunk] = s;
}

// ---------------- K5: bf16 tensor-core partial gram (K-split) ---------------
// 4-stage cp.async ring, ONE barrier per chunk (write stage is always >=2
// ahead of read stage; barrier bounds inter-thread skew to <1 iteration).
__constant__ int c_ti[N_TILES] = {0,0,0,0,1,1,1,2,2,3};
__constant__ int c_tj[N_TILES] = {0,1,2,3,1,2,3,2,3,3};

#define KCHUNK 32
#define NSTAGE 4

__global__ void __launch_bounds__(256, 4) k5_gram() {
    int bx = blockIdx.x;
    int t = bx % N_TILES;
    int slice = bx / N_TILES;
    int c = blockIdx.y;
    int v = blockIdx.z;
    const __nv_bfloat16* __restrict__ x = v ? g_xb : g_xa;
    int ti = c_ti[t], tj = c_tj[t];
    bool diag = (ti == tj);

    __shared__ __nv_bfloat16 As[NSTAGE][KCHUNK][72];
    __shared__ __nv_bfloat16 Bs[NSTAGE][KCHUNK][72];
    __shared__ float red[256];

    int n = g_counts[c];
    int lo  = (int)(((long)n * slice) / KSPLIT);
    int hi  = (int)(((long)n * (slice + 1)) / KSPLIT);
    int cnt = hi - lo;
    int base = g_offsets[c] + lo;

    int tid  = threadIdx.x;
    int lane = tid & 31;
    int warp = tid >> 5;

    int m0 = (warp >> 1) * 16;     // warp's m-block within 64
    int nh = (warp & 1) * 32;      // warp's n-half within 64

    unsigned aBase = (unsigned)__cvta_generic_to_shared(&As[0][0][0]);
    unsigned bBase = diag ? aBase
                          : (unsigned)__cvta_generic_to_shared(&Bs[0][0][0]);
    const unsigned STAGE = KCHUNK * 72 * 2;   // bytes per stage
    int a_row = (lane & 7) + ((lane >> 4) & 1) * 8;          // k within 16
    int a_col = m0 + ((lane >> 3) & 1) * 8;                  // m
    unsigned aAddr = aBase + (unsigned)(a_row * 72 + a_col) * 2u;
    int b_row = (lane & 7) + ((lane >> 3) & 1) * 8;          // k within 16
    int b_col = nh + ((lane >> 4) & 1) * 8;                  // n
    unsigned bAddr0 = bBase + (unsigned)(b_row * 72 + b_col) * 2u;
    unsigned bAddr1 = bAddr0 + 16u * 2u;                     // n-tiles +16

    // staging: one 16B segment per thread (32 rows x 8 segs = 256 tasks)
    int kr  = tid >> 3;    // 0..31
    int seg = tid & 7;     // 0..7

    // colsum assignment (diag blocks): col = tid&63, rows (tid>>6)*8..+7
    int cs_col = tid & 63;
    int cs_r0  = (tid >> 6) * 8;
    float cs = 0.f;

    int nchunks = (cnt + KCHUNK - 1) / KCHUNK;

    #define ISSUE(ci, st) do {                                             \
        int kk = (ci) * KCHUNK + kr;                                       \
        bool pv = kk < cnt;                                                \
        const __nv_bfloat16* rp = x + (long)(base + kk) * D_DIM;           \
        cpa16(&As[st][kr][seg * 8], rp + ti * 64 + seg * 8, pv);           \
        if (!diag)                                                         \
            cpa16(&Bs[st][kr][seg * 8], rp + tj * 64 + seg * 8, pv);       \
    } while (0)

    float acc[4][4] = {};    // [n-tile 0..3][c0..c3]

    ISSUE(0, 0);
    cpa_commit();
    if (nchunks > 1) ISSUE(1, 1);
    cpa_commit();
    for (int ci = 0; ci < nchunks; ci++) {
        if (ci + 2 < nchunks) {
            int st = (ci + 2) & (NSTAGE - 1);
            ISSUE(ci + 2, st);
        }
        cpa_commit();
        cpa_wait2();
        __syncthreads();        // single barrier: data-ready for stage ci
        int st = ci & (NSTAGE - 1);
        unsigned sOff = (unsigned)st * STAGE;
        #pragma unroll
        for (int ks = 0; ks < KCHUNK; ks += 16) {
            unsigned off = sOff + (unsigned)(ks * 72) * 2u;
            unsigned a0, a1, a2, a3;
            unsigned p0, p1, p2, p3;
            unsigned q0, q1, q2, q3;
            ldsm4t(a0, a1, a2, a3, aAddr + off);
            ldsm4t(p0, p1, p2, p3, bAddr0 + off);
            ldsm4t(q0, q1, q2, q3, bAddr1 + off);
            mma16816(acc[0], a0, a1, a2, a3, p0, p1);
            mma16816(acc[1], a0, a1, a2, a3, p2, p3);
            mma16816(acc[2], a0, a1, a2, a3, q0, q1);
            mma16816(acc[3], a0, a1, a2, a3, q2, q3);
        }
        if (diag) {
            #pragma unroll
            for (int u = 0; u < 8; u++)
                cs += __bfloat162float(As[st][cs_r0 + u][cs_col]);
        }
    }

    // ---- write partial gram tile ----
    float* G = g_gram[slice][v][c][t];
    int g  = lane >> 2;       // 0..7
    int tg = lane & 3;        // 0..3
    int r0 = m0 + g, r1 = m0 + g + 8;
    #pragma unroll
    for (int nt = 0; nt < 4; nt++) {
        int col = nh + nt * 8 + 2 * tg;
        *(float2*)&G[r0 * 64 + col] = make_float2(acc[nt][0], acc[nt][1]);
        *(float2*)&G[r1 * 64 + col] = make_float2(acc[nt][2], acc[nt][3]);
    }

    // ---- diag blocks: reduce + write partial colsums ----
    if (diag) {
        __syncthreads();
        red[tid] = cs;
        __syncthreads();
        if (tid < 64)
            g_colsum[slice][v][c][ti * 64 + tid] =
                red[tid] + red[tid + 64] + red[tid + 128] + red[tid + 192];
    }
}

// ---------------- K5b: mean/var from colsum + gram diagonal -----------------
__constant__ int c_diagt[4] = {0, 4, 7, 9};

__global__ void k5b_meanvar() {
    int o = blockIdx.x * 256 + threadIdx.x;   // grid 32 -> 8192 entries
    int d = o & (D_DIM - 1);
    int c = (o >> 8) & (C_CLASSES - 1);
    int v = o >> 12;
    float fn = (float)g_counts[c];
    float colsum = 0.f, Gdd = 0.f;
    int s = d >> 6, dd = d & 63;
    #pragma unroll
    for (int sl = 0; sl < KSPLIT; sl++) {
        colsum += g_colsum[sl][v][c][d];
        Gdd    += g_gram[sl][v][c][c_diagt[s]][dd * 64 + dd];
    }
    float m = colsum / fn;
    g_mean[o] = m;
    g_var[o] = (Gdd - fn * m * m) / (fn - 1.f);
}

// ---------------- K5c: covariance partials from summed gram + means ---------
__global__ void __launch_bounds__(256) k5c_cov() {
    int t = blockIdx.x;
    int c = blockIdx.y;
    int v = blockIdx.z;
    int ti = c_ti[t], tj = c_tj[t];
    bool diag = (ti == tj);

    __shared__ float mi[64], mj[64];
    __shared__ float red[256];
    int tid = threadIdx.x;
    int vc = v * C_CLASSES + c;
    const float* mrow = &g_mean[vc * D_DIM];
    if (tid < 64)        mi[tid]      = mrow[ti * 64 + tid];
    else if (tid < 128)  mj[tid - 64] = mrow[tj * 64 + tid - 64];
    __syncthreads();

    const float* __restrict__ G0 = g_gram[0][v][c][t];
    const float* __restrict__ G1 = g_gram[1][v][c][t];
    float fn = (float)g_counts[c];
    float inv_nm1 = 1.f / (fn - 1.f);
    float wgt_tile = diag ? 1.f : 2.f;

    float sum = 0.f;
    #pragma unroll
    for (int k = 0; k < 16; k++) {
        int idx = tid + k * 256;
        int r = idx >> 6, col = idx & 63;
        float cv = (G0[idx] + G1[idx] - fn * mi[r] * mj[col]) * inv_nm1;
        float w = (diag && r == col) ? 0.f : wgt_tile;
        sum += w * cv * cv;
    }
    sum = block_reduce_256(sum, red);
    if (tid == 0) g_cov_partial[vc * N_TILES + t] = sum;
}

// ---------------- K6: finalize all terms ------------------------------------
__global__ void k6_final(float* __restrict__ out, int N) {
    __shared__ float m[C_CLASSES * D_DIM];
    __shared__ float red[256];
    int tid = threadIdx.x;

    for (int e = tid; e < C_CLASSES * D_DIM; e += 256)
        m[e] = 0.5f * (g_mean[e] + g_mean[C_CLASSES * D_DIM + e]);

    // invariance partials
    float inv_sum = 0.f;
    for (int e = tid; e < CVT_BLOCKS; e += 256) inv_sum += g_inv_partial[e];
    inv_sum = block_reduce_256(inv_sum, red);

    // variance
    float vsum = 0.f;
    for (int e = tid; e < 2 * C_CLASSES * D_DIM; e += 256) {
        float vv = g_var[e];
        vsum += fmaxf(0.f, 1.f - sqrtf(vv + EPS_V));
    }
    vsum = block_reduce_256(vsum, red);

    // covariance
    float csum = 0.f;
    for (int e = tid; e < 2 * C_CLASSES * N_TILES; e += 256)
        csum += g_cov_partial[e];
    csum = block_reduce_256(csum, red);

    // class-discriminative margin (120 pairs)
    float psum = 0.f;
    const int npairs = C_CLASSES * (C_CLASSES - 1) / 2;
    if (tid < npairs) {
        int i = 0, rem = tid;
        while (rem >= C_CLASSES - 1 - i) { rem -= C_CLASSES - 1 - i; i++; }
        int j = i + 1 + rem;
        float d2 = 0.f;
        for (int d = 0; d < D_DIM; d++) {
            float df = m[i * D_DIM + d] - m[j * D_DIM + d];
            d2 += df * df;
        }
        float dist = sqrtf(d2);
        float rr = fmaxf(0.f, ALPHA - dist);
        psum = rr * rr;
    }
    psum = block_reduce_256(psum, red);

    if (tid == 0) {
        float inv_loss   = inv_sum / ((float)N * (float)D_DIM);
        float var_loss   = vsum * 0.5f / ((float)C_CLASSES * (float)D_DIM);
        float cov_loss   = csum * 0.5f / ((float)C_CLASSES * (float)D_DIM);
        float class_loss = psum / (float)npairs;
        out[0] = LAM * inv_loss + MU * var_loss + NU * cov_loss + ALPHA * class_loss;
    }
}

// ---------------- launch -----------------------------------------------------
extern "C" void kernel_launch(void* const* d_in, const int* in_sizes, int n_in,
                              void* d_out, int out_size) {
    const float* za     = (const float*)d_in[0];
    const float* zb     = (const float*)d_in[1];
    const int*   labels = (const int*)d_in[2];
    int N = in_sizes[2];   // labels element count

    k1_hist<<<NCHUNK / 8, 256>>>(labels, N);
    k2_scan<<<1, 512>>>();
    k1b_cvt<<<NCHUNK, 256>>>(za, zb, N);
    k5_gram<<<dim3(N_TILES * KSPLIT, C_CLASSES, 2), 256>>>();
    k5b_meanvar<<<32, 256>>>();
    k5c_cov<<<dim3(N_TILES, C_CLASSES, 2), 256>>>();
    k6_final<<<1, 256>>>((float*)d_out, N);
}

// round 12
// speedup vs baseline: 1.9964x; 1.0558x over previous
#include <cuda_runtime.h>
#include <cuda_bf16.h>
#include <math.h>

// Problem constants (fixed by the benchmark's setup_inputs)
#define C_CLASSES 16
#define D_DIM     256
#define N_MAX     32768
#define N_TILES   10          // upper-triangle 64x64 tiles of a 256x256 gram
#define LAM   25.0f
#define MU    25.0f
#define NU     1.0f
#define ALPHA 50.0f
#define EPS_V  1e-4f

#define NCHUNK (N_MAX / 32)   // 1024 chunks of 32 rows
#define CVT_BLOCKS NCHUNK
#define KSPLIT 3              // K-dimension split of the gram reduction
#define N_PAIRS 5             // tile pairs per (class, view)

// ---------------- scratch (device globals; no allocation allowed) ----------
__device__ int   g_chunk_hist[NCHUNK][C_CLASSES];
__device__ int   g_chunk_base[NCHUNK][C_CLASSES];
__device__ int   g_rank[N_MAX];                     // (label<<16) | rank
__device__ int   g_counts[C_CLASSES];
__device__ int   g_offsets[C_CLASSES];
__device__ float g_mean[2 * C_CLASSES * D_DIM];     // [view][class][d]
__device__ float g_var [2 * C_CLASSES * D_DIM];
__device__ float g_colsum[KSPLIT][2][C_CLASSES][D_DIM];
__device__ float g_gram[KSPLIT][2][C_CLASSES][N_TILES][64 * 64];
__device__ float g_inv_partial[CVT_BLOCKS];
__device__ float g_cov_partial[2 * C_CLASSES * N_TILES];
__device__ __nv_bfloat16 g_xa[N_MAX * D_DIM];       // class-sorted bf16 rows
__device__ __nv_bfloat16 g_xb[N_MAX * D_DIM];

// ---------------- helpers ---------------------------------------------------
__device__ __forceinline__ float block_reduce_256(float v, float* red) {
    int tid = threadIdx.x;
    red[tid] = v;
    __syncthreads();
    #pragma unroll
    for (int s = 128; s > 0; s >>= 1) {
        if (tid < s) red[tid] += red[tid + s];
        __syncthreads();
    }
    float r = red[0];
    __syncthreads();
    return r;
}

__device__ __forceinline__ void ldsm4t(unsigned& r0, unsigned& r1,
                                       unsigned& r2, unsigned& r3,
                                       unsigned addr) {
    asm volatile("ldmatrix.sync.aligned.m8n8.x4.trans.shared.b16 {%0,%1,%2,%3}, [%4];\n"
                 : "=r"(r0), "=r"(r1), "=r"(r2), "=r"(r3) : "r"(addr));
}

__device__ __forceinline__ void mma16816(float* c, unsigned a0, unsigned a1,
                                         unsigned a2, unsigned a3,
                                         unsigned b0, unsigned b1) {
    asm volatile("mma.sync.aligned.m16n8k16.row.col.f32.bf16.bf16.f32 "
                 "{%0,%1,%2,%3}, {%4,%5,%6,%7}, {%8,%9}, {%0,%1,%2,%3};\n"
                 : "+f"(c[0]), "+f"(c[1]), "+f"(c[2]), "+f"(c[3])
                 : "r"(a0), "r"(a1), "r"(a2), "r"(a3), "r"(b0), "r"(b1));
}

__device__ __forceinline__ void cpa16(void* dst, const void* src, bool pred) {
    unsigned d = (unsigned)__cvta_generic_to_shared(dst);
    int sz = pred ? 16 : 0;
    asm volatile("cp.async.cg.shared.global [%0], [%1], 16, %2;\n"
                 :: "r"(d), "l"(src), "r"(sz));
}
__device__ __forceinline__ void cpa_commit() {
    asm volatile("cp.async.commit_group;\n");
}
__device__ __forceinline__ void cpa_wait1() {
    asm volatile("cp.async.wait_group 1;\n");
}

__device__ __forceinline__ unsigned pack_bf162(float x, float y) {
    __nv_bfloat162 h = __floats2bfloat162_rn(x, y);
    return *reinterpret_cast<unsigned*>(&h);
}

// ---------------- K1: per-chunk histogram + per-row rank (ballot) -----------
__global__ void k1_hist(const int* __restrict__ labels, int N) {
    int lane  = threadIdx.x & 31;
    int chunk = blockIdx.x * 8 + (threadIdx.x >> 5);
    int row   = chunk * 32 + lane;
    int lab   = (row < N) ? labels[row] : C_CLASSES;   // sentinel for OOB
    if (lane < C_CLASSES) g_chunk_hist[chunk][lane] = 0;
    __syncwarp();
    unsigned mask = __match_any_sync(0xffffffffu, lab);
    int rank = __popc(mask & ((1u << lane) - 1u));
    int leader = __ffs(mask) - 1;
    if (lab < C_CLASSES) {
        if (lane == leader) g_chunk_hist[chunk][lab] = __popc(mask);
        g_rank[row] = (lab << 16) | rank;
    }
}

// ---------------- K2: two-level scan -> per-chunk class bases ---------------
__global__ void __launch_bounds__(512) k2_scan() {
    __shared__ int ssum[32][C_CLASSES];
    __shared__ int sbase[32][C_CLASSES];
    __shared__ int soff[C_CLASSES];
    int t = threadIdx.x;          // 0..511
    int sb = t >> 4, c = t & 15;  // superblock 0..31, class 0..15
    int s = 0;
    #pragma unroll 4
    for (int k = 0; k < 32; k++) s += g_chunk_hist[sb * 32 + k][c];
    ssum[sb][c] = s;
    __syncthreads();
    if (t < C_CLASSES) {
        int run = 0;
        for (int b = 0; b < 32; b++) { sbase[b][t] = run; run += ssum[b][t]; }
        g_counts[t] = run;
    }
    __syncthreads();
    if (t == 0) {
        int o = 0;
        for (int cc = 0; cc < C_CLASSES; cc++) {
            soff[cc] = o;
            g_offsets[cc] = o;
            o += g_counts[cc];
        }
    }
    __syncthreads();
    int run = soff[c] + sbase[sb][c];
    for (int k = 0; k < 32; k++) {
        int ch = sb * 32 + k;
        g_chunk_base[ch][c] = run;
        run += g_chunk_hist[ch][c];
    }
}

// ---------------- K1b: convert + deterministic sorted scatter + invariance --
__global__ void __launch_bounds__(256) k1b_cvt(const float* __restrict__ za,
                                               const float* __restrict__ zb,
                                               int N) {
    __shared__ float red[256];
    int tid  = threadIdx.x;
    int lane = tid & 31;
    int w    = tid >> 5;
    int chunk = blockIdx.x;

    float s = 0.f;
    #pragma unroll
    for (int i = 0; i < 4; i += 2) {
        int rowA = chunk * 32 + w * 4 + i;
        int rowB = rowA + 1;
        bool vA = rowA < N, vB = rowB < N;

        const float4* paA = (const float4*)(za + (long)rowA * D_DIM);
        const float4* pbA = (const float4*)(zb + (long)rowA * D_DIM);
        const float4* paB = (const float4*)(za + (long)rowB * D_DIM);
        const float4* pbB = (const float4*)(zb + (long)rowB * D_DIM);

        float4 a0A, a1A, b0A, b1A, a0B, a1B, b0B, b1B;
        if (vA) {
            a0A = __ldcs(paA + lane * 2); a1A = __ldcs(paA + lane * 2 + 1);
            b0A = __ldcs(pbA + lane * 2); b1A = __ldcs(pbA + lane * 2 + 1);
        }
        if (vB) {
            a0B = __ldcs(paB + lane * 2); a1B = __ldcs(paB + lane * 2 + 1);
            b0B = __ldcs(pbB + lane * 2); b1B = __ldcs(pbB + lane * 2 + 1);
        }

        if (vA) {
            int lr  = g_rank[rowA];
            int pos = g_chunk_base[chunk][lr >> 16] + (lr & 0xffff);
            float dx = a0A.x - b0A.x, dy = a0A.y - b0A.y,
                  dz = a0A.z - b0A.z, dw = a0A.w - b0A.w;
            s += dx * dx + dy * dy + dz * dz + dw * dw;
            dx = a1A.x - b1A.x; dy = a1A.y - b1A.y;
            dz = a1A.z - b1A.z; dw = a1A.w - b1A.w;
            s += dx * dx + dy * dy + dz * dz + dw * dw;
            uint4 wa, wb;
            wa.x = pack_bf162(a0A.x, a0A.y); wa.y = pack_bf162(a0A.z, a0A.w);
            wa.z = pack_bf162(a1A.x, a1A.y); wa.w = pack_bf162(a1A.z, a1A.w);
            wb.x = pack_bf162(b0A.x, b0A.y); wb.y = pack_bf162(b0A.z, b0A.w);
            wb.z = pack_bf162(b1A.x, b1A.y); wb.w = pack_bf162(b1A.z, b1A.w);
            ((uint4*)(g_xa + (long)pos * D_DIM))[lane] = wa;
            ((uint4*)(g_xb + (long)pos * D_DIM))[lane] = wb;
        }
        if (vB) {
            int lr  = g_rank[rowB];
            int pos = g_chunk_base[chunk][lr >> 16] + (lr & 0xffff);
            float dx = a0B.x - b0B.x, dy = a0B.y - b0B.y,
                  dz = a0B.z - b0B.z, dw = a0B.w - b0B.w;
            s += dx * dx + dy * dy + dz * dz + dw * dw;
            dx = a1B.x - b1B.x; dy = a1B.y - b1B.y;
            dz = a1B.z - b1B.z; dw = a1B.w - b1B.w;
            s += dx * dx + dy * dy + dz * dz + dw * dw;
            uint4 wa, wb;
            wa.x = pack_bf162(a0B.x, a0B.y); wa.y = pack_bf162(a0B.z, a0B.w);
            wa.z = pack_bf162(a1B.x, a1B.y); wa.w = pack_bf162(a1B.z, a1B.w);
            wb.x = pack_bf162(b0B.x, b0B.y); wb.y = pack_bf162(b0B.z, b0B.w);
            wb.z = pack_bf162(b1B.x, b1B.y); wb.w = pack_bf162(b1B.z, b1B.w);
            ((uint4*)(g_xa + (long)pos * D_DIM))[lane] = wa;
            ((uint4*)(g_xb + (long)pos * D_DIM))[lane] = wb;
        }
    }
    s = block_reduce_256(s, red);
    if (tid == 0) g_inv_partial[chunk] = s;
}

// ---------------- K5: bf16 gram, tile-pair blocks, fat warps ----------------
// Block = (pair 0..4, slice, class, view), 128 threads (4 warps).
// Each warp computes 32m x 64n of one of the block's 2 tiles; tiles in a pair
// share smem strips. Pairs: P0=(0,0),(0,1); P1=(0,2),(0,3); P2=(1,1),(1,2);
// P3=(2,2),(2,3); P4=(1,3),(3,3). P0 computes colsums for strips 0,1;
// P3 for strips 2,3.
__constant__ int c_ti[N_TILES] = {0,0,0,0,1,1,1,2,2,3};
__constant__ int c_tj[N_TILES] = {0,1,2,3,1,2,3,2,3,3};
__constant__ int p_t0[N_PAIRS] = {0, 2, 4, 7, 6};   // gram id, tile slot 0
__constant__ int p_t1[N_PAIRS] = {1, 3, 5, 8, 9};   // gram id, tile slot 1
__constant__ int p_strips[N_PAIRS][3] = {{0,1,0},{0,2,3},{1,2,0},{2,3,0},{1,3,0}};
__constant__ int p_nstrips[N_PAIRS] = {2, 3, 2, 2, 2};
__constant__ int p_sa[N_PAIRS][2] = {{0,0},{0,0},{0,0},{0,0},{0,1}};
__constant__ int p_sb[N_PAIRS][2] = {{0,1},{1,2},{0,1},{0,1},{1,1}};
__constant__ int p_cs[N_PAIRS] = {1, 0, 0, 1, 0};

#define KCHUNK 32
#define NSTAGE 3

__global__ void __launch_bounds__(128, 4) k5_gram() {
    int bx    = blockIdx.x;
    int pair  = bx % N_PAIRS;
    int slice = bx / N_PAIRS;
    int c = blockIdx.y;
    int v = blockIdx.z;
    const __nv_bfloat16* __restrict__ x = v ? g_xb : g_xa;

    __shared__ __nv_bfloat16 S[3][NSTAGE][KCHUNK][72];

    int n = g_counts[c];
    int lo  = (int)(((long)n * slice) / KSPLIT);
    int hi  = (int)(((long)n * (slice + 1)) / KSPLIT);
    int cnt = hi - lo;
    int base = g_offsets[c] + lo;

    int tid  = threadIdx.x;
    int lane = tid & 31;
    int warp = tid >> 5;        // 0..3
    int slot = warp >> 1;       // tile slot 0/1
    int m_off = (warp & 1) * 32;

    int nstrips = p_nstrips[pair];
    int s0 = p_strips[pair][0], s1 = p_strips[pair][1], s2 = p_strips[pair][2];
    int sa = p_sa[pair][slot];
    int sb = p_sb[pair][slot];

    unsigned sBase = (unsigned)__cvta_generic_to_shared(&S[0][0][0][0]);
    const unsigned SS = KCHUNK * 72 * 2;   // bytes per (strip, stage)
    int a_row = (lane & 7) + ((lane >> 4) & 1) * 8;
    int a_col = m_off + ((lane >> 3) & 1) * 8;
    unsigned aAddr = sBase + (unsigned)(sa * NSTAGE) * SS
                   + (unsigned)(a_row * 72 + a_col) * 2u;
    int b_row = (lane & 7) + ((lane >> 3) & 1) * 8;
    int b_col = ((lane >> 4) & 1) * 8;
    unsigned bAddr = sBase + (unsigned)(sb * NSTAGE) * SS
                   + (unsigned)(b_row * 72 + b_col) * 2u;

    // colsum assignment: local strip tid>>6 (0/1), column tid&63
    bool docs  = p_cs[pair] != 0;
    int cs_ls  = tid >> 6;
    int cs_col = tid & 63;
    int cs_gs  = p_strips[pair][cs_ls];
    float cs = 0.f;

    int nchunks = (cnt + KCHUNK - 1) / KCHUNK;

    #define ISSUE(ci, st) do {                                              \
        int ntask = nstrips * 256;                                          \
        for (int task = tid; task < ntask; task += 128) {                   \
            int sp  = task >> 8;                                            \
            int w   = task & 255;                                           \
            int kr  = w >> 3;                                               \
            int seg = w & 7;                                                \
            int kk  = (ci) * KCHUNK + kr;                                   \
            bool pv = kk < cnt;                                             \
            int gs  = (sp == 0) ? s0 : ((sp == 1) ? s1 : s2);               \
            cpa16(&S[sp][st][kr][seg * 8],                                  \
                  x + (long)(base + kk) * D_DIM + gs * 64 + seg * 8, pv);   \
        }                                                                   \
    } while (0)

    float acc[2][8][4] = {};   // [m 16-block][n 8-tile][c0..c3]

    ISSUE(0, 0);
    cpa_commit();
    for (int ci = 0; ci < nchunks; ci++) {
        if (ci + 1 < nchunks) {
            int stn = (ci + 1) % NSTAGE;
            ISSUE(ci + 1, stn);
        }
        cpa_commit();
        cpa_wait1();
        __syncthreads();        // single barrier per chunk
        int st = ci % NSTAGE;
        unsigned stOff = (unsigned)st * SS;
        #pragma unroll
        for (int ks = 0; ks < KCHUNK; ks += 16) {
            unsigned off = stOff + (unsigned)(ks * 72) * 2u;
            unsigned a0, a1, a2, a3, a4, a5, a6, a7;
            ldsm4t(a0, a1, a2, a3, aAddr + off);          // m_off..+15
            ldsm4t(a4, a5, a6, a7, aAddr + off + 32u);    // m_off+16..+31
            #pragma unroll
            for (int g = 0; g < 4; g++) {
                unsigned b0, b1, b2, b3;
                ldsm4t(b0, b1, b2, b3, bAddr + off + (unsigned)g * 32u);
                mma16816(acc[0][2 * g],     a0, a1, a2, a3, b0, b1);
                mma16816(acc[0][2 * g + 1], a0, a1, a2, a3, b2, b3);
                mma16816(acc[1][2 * g],     a4, a5, a6, a7, b0, b1);
                mma16816(acc[1][2 * g + 1], a4, a5, a6, a7, b2, b3);
            }
        }
        if (docs) {
            #pragma unroll
            for (int r = 0; r < KCHUNK; r++)
                cs += __bfloat162float(S[cs_ls][st][r][cs_col]);
        }
    }

    // ---- write partial gram tiles ----
    int tgram = slot ? p_t1[pair] : p_t0[pair];
    float* G = g_gram[slice][v][c][tgram];
    int g  = lane >> 2;       // 0..7
    int tg = lane & 3;        // 0..3
    #pragma unroll
    for (int mi = 0; mi < 2; mi++) {
        int r0 = m_off + mi * 16 + g;
        int r1 = r0 + 8;
        #pragma unroll
        for (int nt = 0; nt < 8; nt++) {
            int col = nt * 8 + 2 * tg;
            *(float2*)&G[r0 * 64 + col] = make_float2(acc[mi][nt][0], acc[mi][nt][1]);
            *(float2*)&G[r1 * 64 + col] = make_float2(acc[mi][nt][2], acc[mi][nt][3]);
        }
    }

    // ---- colsum writers (per-thread column sums; no reduction needed) ----
    if (docs)
        g_colsum[slice][v][c][cs_gs * 64 + cs_col] = cs;
}

// ---------------- K5b: mean/var from colsum + gram diagonal -----------------
__constant__ int c_diagt[4] = {0, 4, 7, 9};

__global__ void k5b_meanvar() {
    int o = blockIdx.x * 256 + threadIdx.x;   // grid 32 -> 8192 entries
    int d = o & (D_DIM - 1);
    int c = (o >> 8) & (C_CLASSES - 1);
    int v = o >> 12;
    float fn = (float)g_counts[c];
    float colsum = 0.f, Gdd = 0.f;
    int s = d >> 6, dd = d & 63;
    #pragma unroll
    for (int sl = 0; sl < KSPLIT; sl++) {
        colsum += g_colsum[sl][v][c][d];
        Gdd    += g_gram[sl][v][c][c_diagt[s]][dd * 64 + dd];
    }
    float m = colsum / fn;
    g_mean[o] = m;
    g_var[o] = (Gdd - fn * m * m) / (fn - 1.f);
}

// ---------------- K5c: covariance partials from summed gram + means ---------
__global__ void __launch_bounds__(256) k5c_cov() {
    int t = blockIdx.x;
    int c = blockIdx.y;
    int v = blockIdx.z;
    int ti = c_ti[t], tj = c_tj[t];
    bool diag = (ti == tj);

    __shared__ float mi[64], mj[64];
    __shared__ float red[256];
    int tid = threadIdx.x;
    int vc = v * C_CLASSES + c;
    const float* mrow = &g_mean[vc * D_DIM];
    if (tid < 64)        mi[tid]      = mrow[ti * 64 + tid];
    else if (tid < 128)  mj[tid - 64] = mrow[tj * 64 + tid - 64];
    __syncthreads();

    const float* __restrict__ G0 = g_gram[0][v][c][t];
    const float* __restrict__ G1 = g_gram[1][v][c][t];
    const float* __restrict__ G2 = g_gram[2][v][c][t];
    float fn = (float)g_counts[c];
    float inv_nm1 = 1.f / (fn - 1.f);
    float wgt_tile = diag ? 1.f : 2.f;

    float sum = 0.f;
    #pragma unroll
    for (int k = 0; k < 16; k++) {
        int idx = tid + k * 256;
        int r = idx >> 6, col = idx & 63;
        float cv = (G0[idx] + G1[idx] + G2[idx] - fn * mi[r] * mj[col]) * inv_nm1;
        float w = (diag && r == col) ? 0.f : wgt_tile;
        sum += w * cv * cv;
    }
    sum = block_reduce_256(sum, red);
    if (tid == 0) g_cov_partial[vc * N_TILES + t] = sum;
}

// ---------------- K6: finalize all terms ------------------------------------
__global__ void k6_final(float* __restrict__ out, int N) {
    __shared__ float m[C_CLASSES * D_DIM];
    __shared__ float red[256];
    int tid = threadIdx.x;

    for (int e = tid; e < C_CLASSES * D_DIM; e += 256)
        m[e] = 0.5f * (g_mean[e] + g_mean[C_CLASSES * D_DIM + e]);

    // invariance partials
    float inv_sum = 0.f;
    for (int e = tid; e < CVT_BLOCKS; e += 256) inv_sum += g_inv_partial[e];
    inv_sum = block_reduce_256(inv_sum, red);

    // variance
    float vsum = 0.f;
    for (int e = tid; e < 2 * C_CLASSES * D_DIM; e += 256) {
        float vv = g_var[e];
        vsum += fmaxf(0.f, 1.f - sqrtf(vv + EPS_V));
    }
    vsum = block_reduce_256(vsum, red);

    // covariance
    float csum = 0.f;
    for (int e = tid; e < 2 * C_CLASSES * N_TILES; e += 256)
        csum += g_cov_partial[e];
    csum = block_reduce_256(csum, red);

    // class-discriminative margin (120 pairs)
    float psum = 0.f;
    const int npairs = C_CLASSES * (C_CLASSES - 1) / 2;
    if (tid < npairs) {
        int i = 0, rem = tid;
        while (rem >= C_CLASSES - 1 - i) { rem -= C_CLASSES - 1 - i; i++; }
        int j = i + 1 + rem;
        float d2 = 0.f;
        for (int d = 0; d < D_DIM; d++) {
            float df = m[i * D_DIM + d] - m[j * D_DIM + d];
            d2 += df * df;
        }
        float dist = sqrtf(d2);
        float rr = fmaxf(0.f, ALPHA - dist);
        psum = rr * rr;
    }
    psum = block_reduce_256(psum, red);

    if (tid == 0) {
        float inv_loss   = inv_sum / ((float)N * (float)D_DIM);
        float var_loss   = vsum * 0.5f / ((float)C_CLASSES * (float)D_DIM);
        float cov_loss   = csum * 0.5f / ((float)C_CLASSES * (float)D_DIM);
        float class_loss = psum / (float)npairs;
        out[0] = LAM * inv_loss + MU * var_loss + NU * cov_loss + ALPHA * class_loss;
    }
}

// ---------------- launch -----------------------------------------------------
extern "C" void kernel_launch(void* const* d_in, const int* in_sizes, int n_in,
                              void* d_out, int out_size) {
    const float* za     = (const float*)d_in[0];
    const float* zb     = (const float*)d_in[1];
    const int*   labels = (const int*)d_in[2];
    int N = in_sizes[2];   // labels element count

    k1_hist<<<NCHUNK / 8, 256>>>(labels, N);
    k2_scan<<<1, 512>>>();
    k1b_cvt<<<NCHUNK, 256>>>(za, zb, N);
    k5_gram<<<dim3(N_PAIRS * KSPLIT, C_CLASSES, 2), 128>>>();
    k5b_meanvar<<<32, 256>>>();
    k5c_cov<<<dim3(N_TILES, C_CLASSES, 2), 256>>>();
    k6_final<<<1, 256>>>((float*)d_out, N);
}